// round 2
// baseline (speedup 1.0000x reference)
#include <cuda_runtime.h>
#include <math.h>

#define HH 64
#define WW 64
#define HWP 4096
#define BB 4
#define C1 128
#define C2 256
#define NK 9

// -------- device scratch (static globals: allocation is forbidden) --------
__device__ float g_xp[BB * C2 * HWP];        // pointwise+BN output  (16.8 MB)
__device__ float g_off[BB * 2 * NK * HWP];   // offset conv output   (1.2 MB)
__device__ float g_dcnt[NK * C2 * C2];       // dcn_w transposed [n][c][o] (2.36 MB)
__device__ float g_pwt[C1 * C2];             // pw_w transposed [c][o]
__device__ float g_scale[C2];
__device__ float g_bias[C2];

// -------- f32x2 helpers (FFMA2: 2x fp32 FMA per instruction) --------
__device__ __forceinline__ void fma2(unsigned long long& d, unsigned long long a,
                                     unsigned long long b) {
    asm("fma.rn.f32x2 %0, %1, %2, %0;" : "+l"(d) : "l"(a), "l"(b));
}
__device__ __forceinline__ unsigned long long packf2(float lo, float hi) {
    unsigned long long r;
    asm("mov.b64 %0, {%1, %2};" : "=l"(r) : "f"(lo), "f"(hi));
    return r;
}
__device__ __forceinline__ void unpackf2(float& lo, float& hi, unsigned long long v) {
    asm("mov.b64 {%0, %1}, %2;" : "=f"(lo), "=f"(hi) : "l"(v));
}

// ======================= prep kernels =======================
__global__ void prep_bn(const float* __restrict__ gamma, const float* __restrict__ beta,
                        const float* __restrict__ mean, const float* __restrict__ var) {
    int o = threadIdx.x;
    float s = gamma[o] * rsqrtf(var[o] + 1e-5f);
    g_scale[o] = s;
    g_bias[o] = beta[o] - mean[o] * s;
}

__global__ void prep_pwt(const float* __restrict__ pw) {
    int c = blockIdx.x;       // 0..127
    int o = threadIdx.x;      // 0..255
    g_pwt[c * C2 + o] = pw[o * C1 + c];
}

__global__ void prep_dcnt(const float* __restrict__ dcn) {
    int c = blockIdx.x;       // 0..255
    int n = blockIdx.y;       // 0..8
    int o = threadIdx.x;      // 0..255
    g_dcnt[(n * C2 + c) * C2 + o] = dcn[(o * C2 + c) * NK + n];
}

// ======================= stage 1: pointwise conv + BN =======================
// block: 256 threads, tile = 16 pixels x 256 out channels, one batch slice.
__global__ void __launch_bounds__(256) pw_bn_kernel(const float* __restrict__ x) {
    __shared__ __align__(16) float sx[C1 * 16];    // [c][p]   8 KB
    __shared__ __align__(16) float spw[32 * C2];   // [c][o]  32 KB
    int t = threadIdx.x;
    int b = blockIdx.y;
    int pix0 = blockIdx.x * 16;

    // load x tile [128 c][16 p]
#pragma unroll
    for (int i = 0; i < 8; i++) {
        int j = t + i * 256;
        int c = j >> 4, p = j & 15;
        sx[j] = x[(b * C1 + c) * HWP + pix0 + p];
    }

    int obase = (t & 63) * 4;
    int pbase = (t >> 6) * 4;
    float acc[4][4];
#pragma unroll
    for (int i = 0; i < 4; i++)
#pragma unroll
        for (int j = 0; j < 4; j++) acc[i][j] = 0.f;

    for (int cc = 0; cc < C1; cc += 32) {
        __syncthreads();
#pragma unroll
        for (int i = 0; i < 32; i++) spw[i * C2 + t] = g_pwt[(cc + i) * C2 + t];
        __syncthreads();
#pragma unroll 8
        for (int c = 0; c < 32; c++) {
            float4 w4 = *(const float4*)&spw[c * C2 + obase];
            float4 x4 = *(const float4*)&sx[(cc + c) * 16 + pbase];
            acc[0][0] += w4.x * x4.x; acc[0][1] += w4.x * x4.y;
            acc[0][2] += w4.x * x4.z; acc[0][3] += w4.x * x4.w;
            acc[1][0] += w4.y * x4.x; acc[1][1] += w4.y * x4.y;
            acc[1][2] += w4.y * x4.z; acc[1][3] += w4.y * x4.w;
            acc[2][0] += w4.z * x4.x; acc[2][1] += w4.z * x4.y;
            acc[2][2] += w4.z * x4.z; acc[2][3] += w4.z * x4.w;
            acc[3][0] += w4.w * x4.x; acc[3][1] += w4.w * x4.y;
            acc[3][2] += w4.w * x4.z; acc[3][3] += w4.w * x4.w;
        }
    }
#pragma unroll
    for (int oo = 0; oo < 4; oo++) {
        int o = obase + oo;
        float s = g_scale[o], bi = g_bias[o];
#pragma unroll
        for (int pp = 0; pp < 4; pp++)
            g_xp[(b * C2 + o) * HWP + pix0 + pbase + pp] = acc[oo][pp] * s + bi;
    }
}

// ======================= stage 2: 3x3 offset conv =======================
// block per (b, h): 288 threads = 9 m-pairs x 32 w-lanes; each thread 2m x 2w.
__global__ void __launch_bounds__(288) offconv_kernel(const float* __restrict__ off_w,
                                                      const float* __restrict__ off_b) {
    __shared__ float sw[18 * 288];     // [m][c(32)*9+tap]  20.7 KB
    __shared__ float sx[32 * 198];     // [c][dy(3)][66 w]  25.3 KB
    int t = threadIdx.x;
    int b = blockIdx.y;
    int h = blockIdx.x;
    int wlo = t & 31;
    int midx = t >> 5;  // 0..8

    float acc00 = 0.f, acc01 = 0.f, acc10 = 0.f, acc11 = 0.f;

    for (int cc = 0; cc < C2; cc += 32) {
        __syncthreads();
        // weights: off_w[m][cc..cc+31][3][3] -> sw[m*288 + (c*9+tap)]
#pragma unroll
        for (int m = 0; m < 18; m++)
            sw[m * 288 + t] = off_w[m * (C2 * 9) + cc * 9 + t];
        // xp halo tile (zero padded)
        for (int j = t; j < 32 * 198; j += 288) {
            int c = j / 198;
            int r = j % 198;
            int dy = r / 66;
            int wx = (r % 66) - 1;
            int hh = h - 1 + dy;
            float v = 0.f;
            if ((unsigned)hh < 64u && (unsigned)wx < 64u)
                v = g_xp[(b * C2 + cc + c) * HWP + hh * WW + wx];
            sx[j] = v;
        }
        __syncthreads();
        for (int c = 0; c < 32; c++) {
            const float* xr = &sx[c * 198];
            const float* wa = &sw[midx * 288 + c * 9];
            const float* wb = &sw[(midx + 9) * 288 + c * 9];
#pragma unroll
            for (int dy = 0; dy < 3; dy++) {
#pragma unroll
                for (int dx = 0; dx < 3; dx++) {
                    float v0 = xr[dy * 66 + wlo + dx];
                    float v1 = xr[dy * 66 + wlo + 32 + dx];
                    float a = wa[dy * 3 + dx];
                    float bw = wb[dy * 3 + dx];
                    acc00 += a * v0;  acc01 += a * v1;
                    acc10 += bw * v0; acc11 += bw * v1;
                }
            }
        }
    }
    float ba = off_b[midx], bb2 = off_b[midx + 9];
    int base = (b * 18 + midx) * HWP + h * WW;
    g_off[base + wlo] = acc00 + ba;
    g_off[base + wlo + 32] = acc01 + ba;
    int base2 = (b * 18 + midx + 9) * HWP + h * WW;
    g_off[base2 + wlo] = acc10 + bb2;
    g_off[base2 + wlo + 32] = acc11 + bb2;
}

// ======================= stage 3: deformable sample + einsum + SiLU =======================
// block: 32 pixels x 256 out channels; 256 threads.
// Per tap n: thread=channel bilinear gather into smem (pixel-paired for f32x2),
// then K=256 GEMM in 4 chunks of 64 with 4o x 8p register tile via FFMA2.
__global__ void __launch_bounds__(256, 2) dcn_kernel(float* __restrict__ out) {
    extern __shared__ __align__(16) float smem[];
    float* sW = smem;                       // [64 c][256 o]           65536 B
    float* sS = smem + 64 * C2;             // pairs: ((pp*258+c)*2+l) 33024 B
    float* cf = sS + 16 * 258 * 2;          // wy[32], wx[32]
    int* ci = (int*)(cf + 64);              // x0[32] x1[32] y0o[32] y1o[32]

    int t = threadIdx.x;
    int b = blockIdx.y;
    int pix0 = blockIdx.x * 32;
    int obase = (t & 63) << 2;
    int pg4 = (t >> 6) << 2;  // first pixel-pair index of this thread's group

    unsigned long long acc[4][4];
#pragma unroll
    for (int i = 0; i < 4; i++)
#pragma unroll
        for (int j = 0; j < 4; j++) acc[i][j] = 0ull;

    const float* xplane = &g_xp[(b * C2 + t) * HWP];  // this thread's channel plane

    for (int n = 0; n < NK; n++) {
        __syncthreads();
        if (t < 32) {
            int pix = pix0 + t;
            int h = pix >> 6, w = pix & 63;
            float oy = g_off[(b * 18 + n) * HWP + pix];
            float ox = g_off[(b * 18 + n + 9) * HWP + pix];
            float py = (float)h + (float)(n / 3 - 1) + oy;
            float px = (float)w + (float)(n % 3 - 1) + ox;
            py = fminf(fmaxf(py, 0.f), 63.f);
            px = fminf(fmaxf(px, 0.f), 63.f);
            float y0f = floorf(py), x0f = floorf(px);
            int y0 = (int)y0f, x0 = (int)x0f;
            int y1 = min(y0 + 1, 63), x1 = min(x0 + 1, 63);
            cf[t] = py - y0f;       // wy
            cf[32 + t] = px - x0f;  // wx
            ci[t] = x0;
            ci[32 + t] = x1;
            ci[64 + t] = y0 * WW;
            ci[96 + t] = y1 * WW;
        }
        __syncthreads();
        // sample 32 pixels for channel t
#pragma unroll 4
        for (int p = 0; p < 32; p++) {
            int x0 = ci[p], x1 = ci[32 + p];
            int y0o = ci[64 + p], y1o = ci[96 + p];
            float wy = cf[p], wx = cf[32 + p];
            float v00 = xplane[y0o + x0];
            float v01 = xplane[y0o + x1];
            float v10 = xplane[y1o + x0];
            float v11 = xplane[y1o + x1];
            float a = v00 + wx * (v01 - v00);
            float bq = v10 + wx * (v11 - v10);
            float s = a + wy * (bq - a);
            sS[(((p >> 1) * 258 + t) << 1) + (p & 1)] = s;
        }

        const float4* wsrc = (const float4*)&g_dcnt[n * C2 * C2];
        float4* wdst = (float4*)sW;
        for (int kc = 0; kc < 4; kc++) {
            __syncthreads();
#pragma unroll
            for (int i = 0; i < 16; i++)
                wdst[i * 256 + t] = wsrc[kc * 4096 + i * 256 + t];
            __syncthreads();
#pragma unroll 4
            for (int c = 0; c < 64; c++) {
                float4 w4 = *(const float4*)&sW[c * C2 + obase];
                unsigned long long w2a = packf2(w4.x, w4.x);
                unsigned long long w2b = packf2(w4.y, w4.y);
                unsigned long long w2c = packf2(w4.z, w4.z);
                unsigned long long w2d = packf2(w4.w, w4.w);
                int cg = kc * 64 + c;
                unsigned long long s0 = *(const unsigned long long*)&sS[((pg4 + 0) * 258 + cg) << 1];
                unsigned long long s1 = *(const unsigned long long*)&sS[((pg4 + 1) * 258 + cg) << 1];
                unsigned long long s2 = *(const unsigned long long*)&sS[((pg4 + 2) * 258 + cg) << 1];
                unsigned long long s3 = *(const unsigned long long*)&sS[((pg4 + 3) * 258 + cg) << 1];
                fma2(acc[0][0], w2a, s0); fma2(acc[0][1], w2a, s1);
                fma2(acc[0][2], w2a, s2); fma2(acc[0][3], w2a, s3);
                fma2(acc[1][0], w2b, s0); fma2(acc[1][1], w2b, s1);
                fma2(acc[1][2], w2b, s2); fma2(acc[1][3], w2b, s3);
                fma2(acc[2][0], w2c, s0); fma2(acc[2][1], w2c, s1);
                fma2(acc[2][2], w2c, s2); fma2(acc[2][3], w2c, s3);
                fma2(acc[3][0], w2d, s0); fma2(acc[3][1], w2d, s1);
                fma2(acc[3][2], w2d, s2); fma2(acc[3][3], w2d, s3);
            }
        }
    }

    // epilogue: SiLU + store
#pragma unroll
    for (int oo = 0; oo < 4; oo++) {
        int o = obase + oo;
        float* orow = &out[(b * C2 + o) * HWP + pix0];
#pragma unroll
        for (int j = 0; j < 4; j++) {
            float f0, f1;
            unpackf2(f0, f1, acc[oo][j]);
            int p = (pg4 + j) << 1;
            orow[p] = f0 / (1.f + __expf(-f0));
            orow[p + 1] = f1 / (1.f + __expf(-f1));
        }
    }
}

// ======================= launch =======================
extern "C" void kernel_launch(void* const* d_in, const int* in_sizes, int n_in,
                              void* d_out, int out_size) {
    const float* x = (const float*)d_in[0];
    const float* pw_w = (const float*)d_in[1];
    const float* gamma = (const float*)d_in[2];
    const float* beta = (const float*)d_in[3];
    const float* mean = (const float*)d_in[4];
    const float* var = (const float*)d_in[5];
    const float* off_w = (const float*)d_in[6];
    const float* off_b = (const float*)d_in[7];
    const float* dcn_w = (const float*)d_in[8];
    float* out = (float*)d_out;

    (void)in_sizes; (void)n_in; (void)out_size;

    cudaFuncSetAttribute(dcn_kernel, cudaFuncAttributeMaxDynamicSharedMemorySize, 100352);

    prep_bn<<<1, 256>>>(gamma, beta, mean, var);
    prep_pwt<<<C1, 256>>>(pw_w);
    prep_dcnt<<<dim3(C2, NK), 256>>>(dcn_w);
    pw_bn_kernel<<<dim3(256, BB), 256>>>(x);
    offconv_kernel<<<dim3(HH, BB), 288>>>(off_w, off_b);
    dcn_kernel<<<dim3(128, BB), 256, 100352>>>(out);
}

// round 3
// speedup vs baseline: 1.8365x; 1.8365x over previous
#include <cuda_runtime.h>
#include <math.h>

#define HH 64
#define WW 64
#define HWP 4096
#define BB 4
#define C1 128
#define C2 256
#define NK 9

typedef unsigned long long ull;

// -------- device scratch (static globals: allocation is forbidden) --------
__device__ float g_xp[BB * C2 * HWP];        // pointwise+BN output  (16.8 MB)
__device__ float g_off[BB * 2 * NK * HWP];   // offset conv output   (1.2 MB)
__device__ float g_dcnt[NK * C2 * C2];       // dcn_w transposed [n][c][o] (2.36 MB)
__device__ float g_pwt[C1 * C2];             // pw_w transposed [c][o]
__device__ float g_scale[C2];
__device__ float g_bias[C2];

// -------- f32x2 helpers (FFMA2: 2x fp32 FMA per instruction) --------
__device__ __forceinline__ void fma2(ull& d, ull a, ull b) {
    asm("fma.rn.f32x2 %0, %1, %2, %0;" : "+l"(d) : "l"(a), "l"(b));
}
__device__ __forceinline__ ull packf2(float lo, float hi) {
    ull r;
    asm("mov.b64 %0, {%1, %2};" : "=l"(r) : "f"(lo), "f"(hi));
    return r;
}
__device__ __forceinline__ void unpackf2(float& lo, float& hi, ull v) {
    asm("mov.b64 {%0, %1}, %2;" : "=f"(lo), "=f"(hi) : "l"(v));
}

// ======================= prep kernels =======================
__global__ void prep_bn(const float* __restrict__ gamma, const float* __restrict__ beta,
                        const float* __restrict__ mean, const float* __restrict__ var) {
    int o = threadIdx.x;
    float s = gamma[o] * rsqrtf(var[o] + 1e-5f);
    g_scale[o] = s;
    g_bias[o] = beta[o] - mean[o] * s;
}

__global__ void prep_pwt(const float* __restrict__ pw) {
    int c = blockIdx.x;       // 0..127
    int o = threadIdx.x;      // 0..255
    g_pwt[c * C2 + o] = pw[o * C1 + c];
}

__global__ void prep_dcnt(const float* __restrict__ dcn) {
    int c = blockIdx.x;       // 0..255
    int n = blockIdx.y;       // 0..8
    int o = threadIdx.x;      // 0..255
    g_dcnt[(n * C2 + c) * C2 + o] = dcn[(o * C2 + c) * NK + n];
}

// ======================= stage 1: pointwise conv + BN =======================
__global__ void __launch_bounds__(256) pw_bn_kernel(const float* __restrict__ x) {
    __shared__ __align__(16) float sx[C1 * 16];    // [c][p]   8 KB
    __shared__ __align__(16) float spw[32 * C2];   // [c][o]  32 KB
    int t = threadIdx.x;
    int b = blockIdx.y;
    int pix0 = blockIdx.x * 16;

#pragma unroll
    for (int i = 0; i < 8; i++) {
        int j = t + i * 256;
        int c = j >> 4, p = j & 15;
        sx[j] = x[(b * C1 + c) * HWP + pix0 + p];
    }

    int obase = (t & 63) * 4;
    int pbase = (t >> 6) * 4;
    float acc[4][4];
#pragma unroll
    for (int i = 0; i < 4; i++)
#pragma unroll
        for (int j = 0; j < 4; j++) acc[i][j] = 0.f;

    for (int cc = 0; cc < C1; cc += 32) {
        __syncthreads();
#pragma unroll
        for (int i = 0; i < 32; i++) spw[i * C2 + t] = g_pwt[(cc + i) * C2 + t];
        __syncthreads();
#pragma unroll 8
        for (int c = 0; c < 32; c++) {
            float4 w4 = *(const float4*)&spw[c * C2 + obase];
            float4 x4 = *(const float4*)&sx[(cc + c) * 16 + pbase];
            acc[0][0] += w4.x * x4.x; acc[0][1] += w4.x * x4.y;
            acc[0][2] += w4.x * x4.z; acc[0][3] += w4.x * x4.w;
            acc[1][0] += w4.y * x4.x; acc[1][1] += w4.y * x4.y;
            acc[1][2] += w4.y * x4.z; acc[1][3] += w4.y * x4.w;
            acc[2][0] += w4.z * x4.x; acc[2][1] += w4.z * x4.y;
            acc[2][2] += w4.z * x4.z; acc[2][3] += w4.z * x4.w;
            acc[3][0] += w4.w * x4.x; acc[3][1] += w4.w * x4.y;
            acc[3][2] += w4.w * x4.z; acc[3][3] += w4.w * x4.w;
        }
    }
#pragma unroll
    for (int oo = 0; oo < 4; oo++) {
        int o = obase + oo;
        float s = g_scale[o], bi = g_bias[o];
#pragma unroll
        for (int pp = 0; pp < 4; pp++)
            g_xp[(b * C2 + o) * HWP + pix0 + pbase + pp] = acc[oo][pp] * s + bi;
    }
}

// ======================= stage 2: 3x3 offset conv =======================
__global__ void __launch_bounds__(288) offconv_kernel(const float* __restrict__ off_w,
                                                      const float* __restrict__ off_b) {
    __shared__ float sw[18 * 288];     // [m][c(32)*9+tap]  20.7 KB
    __shared__ float sx[32 * 198];     // [c][dy(3)][66 w]  25.3 KB
    int t = threadIdx.x;
    int b = blockIdx.y;
    int h = blockIdx.x;
    int wlo = t & 31;
    int midx = t >> 5;  // 0..8

    float acc00 = 0.f, acc01 = 0.f, acc10 = 0.f, acc11 = 0.f;

    for (int cc = 0; cc < C2; cc += 32) {
        __syncthreads();
#pragma unroll
        for (int m = 0; m < 18; m++)
            sw[m * 288 + t] = off_w[m * (C2 * 9) + cc * 9 + t];
        for (int j = t; j < 32 * 198; j += 288) {
            int c = j / 198;
            int r = j % 198;
            int dy = r / 66;
            int wx = (r % 66) - 1;
            int hh = h - 1 + dy;
            float v = 0.f;
            if ((unsigned)hh < 64u && (unsigned)wx < 64u)
                v = g_xp[(b * C2 + cc + c) * HWP + hh * WW + wx];
            sx[j] = v;
        }
        __syncthreads();
        for (int c = 0; c < 32; c++) {
            const float* xr = &sx[c * 198];
            const float* wa = &sw[midx * 288 + c * 9];
            const float* wb = &sw[(midx + 9) * 288 + c * 9];
#pragma unroll
            for (int dy = 0; dy < 3; dy++) {
#pragma unroll
                for (int dx = 0; dx < 3; dx++) {
                    float v0 = xr[dy * 66 + wlo + dx];
                    float v1 = xr[dy * 66 + wlo + 32 + dx];
                    float a = wa[dy * 3 + dx];
                    float bw = wb[dy * 3 + dx];
                    acc00 += a * v0;  acc01 += a * v1;
                    acc10 += bw * v0; acc11 += bw * v1;
                }
            }
        }
    }
    float ba = off_b[midx], bb2 = off_b[midx + 9];
    int base = (b * 18 + midx) * HWP + h * WW;
    g_off[base + wlo] = acc00 + ba;
    g_off[base + wlo + 32] = acc01 + ba;
    int base2 = (b * 18 + midx + 9) * HWP + h * WW;
    g_off[base2 + wlo] = acc10 + bb2;
    g_off[base2 + wlo + 32] = acc11 + bb2;
}

// ======================= stage 3: deformable sample + einsum + SiLU =======================
// block = one image row (64 pixels) x all 256 out channels; 256 threads; 1 block/SM.
// Gather: lane = pixel (coalesced LDG, offsets are tiny so addresses ~consecutive),
//         warp wd owns channels wd*32..wd*32+31.
// GEMM:   thread tile = 8 o (two 4-float halves at +0/+128, conflict-free LDS.128)
//         x 4 pixel-pairs (8 pixels) via FFMA2. sS pitch 257 pairs: conflict-free STS+LDS.
__global__ void __launch_bounds__(256, 1) dcn_kernel(float* __restrict__ out) {
    extern __shared__ __align__(16) float smem[];
    float* sW = smem;                 // [64 c][256 o]              16384 f
    float* sS = smem + 16384;         // [pp(32) pitch 257][c][2]   16448 f
    float* cf = sS + 16448;           // wy[64], wx[64]
    int* ci = (int*)(cf + 128);       // x0[64] x1[64] y0o[64] y1o[64]

    int t = threadIdx.x;
    int b = blockIdx.y;
    int h = blockIdx.x;
    int lane = t & 31;
    int wd = t >> 5;       // warp id 0..7
    int og = t & 31;       // o-group: o = og*4..og*4+3 and +128
    int pg = wd * 4;       // first pixel-pair (0..28)

    ull acc[2][4][4];
#pragma unroll
    for (int hf = 0; hf < 2; hf++)
#pragma unroll
        for (int i = 0; i < 4; i++)
#pragma unroll
            for (int j = 0; j < 4; j++) acc[hf][i][j] = 0ull;

    const float* xpb = g_xp + (size_t)b * C2 * HWP;

    for (int n = 0; n < NK; n++) {
        // ---- coords for 64 pixels of this row ----
        if (t < 64) {
            int pix = h * WW + t;
            float oy = g_off[(b * 18 + n) * HWP + pix];
            float ox = g_off[(b * 18 + n + 9) * HWP + pix];
            float py = (float)h + (float)(n / 3 - 1) + oy;
            float px = (float)t + (float)(n % 3 - 1) + ox;
            py = fminf(fmaxf(py, 0.f), 63.f);
            px = fminf(fmaxf(px, 0.f), 63.f);
            float y0f = floorf(py), x0f = floorf(px);
            int y0 = (int)y0f, x0 = (int)x0f;
            int y1 = min(y0 + 1, 63), x1 = min(x0 + 1, 63);
            cf[t] = py - y0f;
            cf[64 + t] = px - x0f;
            ci[t] = x0;
            ci[64 + t] = x1;
            ci[128 + t] = y0 * WW;
            ci[192 + t] = y1 * WW;
        }
        __syncthreads();   // coords ready; also: previous tap's GEMM reads of sS done

        // ---- gather: this warp = channels [wd*32, wd*32+32), lane = pixel ----
        {
            const float* pl0 = xpb + (size_t)(wd * 32) * HWP;
#pragma unroll
            for (int ph = 0; ph < 2; ph++) {
                int p = ph * 32 + lane;
                int x0 = ci[p], x1 = ci[64 + p];
                int y0o = ci[128 + p], y1o = ci[192 + p];
                float wy = cf[p], wx = cf[64 + p];
                int pairbase = (p >> 1) * 514 + (p & 1);
                const float* plane = pl0;
#pragma unroll 4
                for (int c = 0; c < 32; c++) {
                    float v00 = plane[y0o + x0];
                    float v01 = plane[y0o + x1];
                    float v10 = plane[y1o + x0];
                    float v11 = plane[y1o + x1];
                    plane += HWP;
                    float a = v00 + wx * (v01 - v00);
                    float bq = v10 + wx * (v11 - v10);
                    sS[pairbase + (wd * 32 + c) * 2] = a + wy * (bq - a);
                }
            }
        }

        const float4* wsrc = (const float4*)(g_dcnt + n * C2 * C2);
        float4* wdst = (float4*)sW;
        for (int kc = 0; kc < 4; kc++) {
            __syncthreads();    // kc>0: prior compute done before sW overwrite; kc==0: gather done
#pragma unroll
            for (int i = 0; i < 16; i++)
                wdst[i * 256 + t] = wsrc[kc * 4096 + i * 256 + t];
            __syncthreads();
            int sb0 = pg * 514 + kc * 128;   // sS float index for pair pg, channel kc*64
#pragma unroll 4
            for (int c = 0; c < 64; c++) {
                float4 wa = *(const float4*)&sW[c * 256 + og * 4];
                float4 wb = *(const float4*)&sW[c * 256 + 128 + og * 4];
                ull s0 = *(const ull*)&sS[sb0 + c * 2];
                ull s1 = *(const ull*)&sS[sb0 + 514 + c * 2];
                ull s2 = *(const ull*)&sS[sb0 + 1028 + c * 2];
                ull s3 = *(const ull*)&sS[sb0 + 1542 + c * 2];
                ull w0 = packf2(wa.x, wa.x);
                ull w1 = packf2(wa.y, wa.y);
                ull w2 = packf2(wa.z, wa.z);
                ull w3 = packf2(wa.w, wa.w);
                fma2(acc[0][0][0], w0, s0); fma2(acc[0][0][1], w0, s1);
                fma2(acc[0][0][2], w0, s2); fma2(acc[0][0][3], w0, s3);
                fma2(acc[0][1][0], w1, s0); fma2(acc[0][1][1], w1, s1);
                fma2(acc[0][1][2], w1, s2); fma2(acc[0][1][3], w1, s3);
                fma2(acc[0][2][0], w2, s0); fma2(acc[0][2][1], w2, s1);
                fma2(acc[0][2][2], w2, s2); fma2(acc[0][2][3], w2, s3);
                fma2(acc[0][3][0], w3, s0); fma2(acc[0][3][1], w3, s1);
                fma2(acc[0][3][2], w3, s2); fma2(acc[0][3][3], w3, s3);
                ull w4 = packf2(wb.x, wb.x);
                ull w5 = packf2(wb.y, wb.y);
                ull w6 = packf2(wb.z, wb.z);
                ull w7 = packf2(wb.w, wb.w);
                fma2(acc[1][0][0], w4, s0); fma2(acc[1][0][1], w4, s1);
                fma2(acc[1][0][2], w4, s2); fma2(acc[1][0][3], w4, s3);
                fma2(acc[1][1][0], w5, s0); fma2(acc[1][1][1], w5, s1);
                fma2(acc[1][1][2], w5, s2); fma2(acc[1][1][3], w5, s3);
                fma2(acc[1][2][0], w6, s0); fma2(acc[1][2][1], w6, s1);
                fma2(acc[1][2][2], w6, s2); fma2(acc[1][2][3], w6, s3);
                fma2(acc[1][3][0], w7, s0); fma2(acc[1][3][1], w7, s1);
                fma2(acc[1][3][2], w7, s2); fma2(acc[1][3][3], w7, s3);
            }
        }
    }

    // ---- epilogue: SiLU + store ----
#pragma unroll
    for (int hf = 0; hf < 2; hf++) {
#pragma unroll
        for (int ow = 0; ow < 4; ow++) {
            int o = og * 4 + ow + hf * 128;
            float* orow = &out[(size_t)(b * C2 + o) * HWP + h * WW];
#pragma unroll
            for (int j = 0; j < 4; j++) {
                float f0, f1;
                unpackf2(f0, f1, acc[hf][ow][j]);
                int p = (pg + j) * 2;
                orow[p] = f0 / (1.f + __expf(-f0));
                orow[p + 1] = f1 / (1.f + __expf(-f1));
            }
        }
    }
}

// ======================= launch =======================
extern "C" void kernel_launch(void* const* d_in, const int* in_sizes, int n_in,
                              void* d_out, int out_size) {
    const float* x = (const float*)d_in[0];
    const float* pw_w = (const float*)d_in[1];
    const float* gamma = (const float*)d_in[2];
    const float* beta = (const float*)d_in[3];
    const float* mean = (const float*)d_in[4];
    const float* var = (const float*)d_in[5];
    const float* off_w = (const float*)d_in[6];
    const float* off_b = (const float*)d_in[7];
    const float* dcn_w = (const float*)d_in[8];
    float* out = (float*)d_out;

    (void)in_sizes; (void)n_in; (void)out_size;

    static int cfg_done = 0;
    cudaFuncSetAttribute(dcn_kernel, cudaFuncAttributeMaxDynamicSharedMemorySize, 135168);
    (void)cfg_done;

    prep_bn<<<1, 256>>>(gamma, beta, mean, var);
    prep_pwt<<<C1, 256>>>(pw_w);
    prep_dcnt<<<dim3(C2, NK), 256>>>(dcn_w);
    pw_bn_kernel<<<dim3(256, BB), 256>>>(x);
    offconv_kernel<<<dim3(HH, BB), 288>>>(off_w, off_b);
    dcn_kernel<<<dim3(HH, BB), 256, 135168>>>(out);
}

// round 8
// speedup vs baseline: 3.3834x; 1.8423x over previous
#include <cuda_runtime.h>
#include <cuda_bf16.h>
#include <math.h>

#define HH 64
#define WW 64
#define HWP 4096
#define BB 4
#define C1 128
#define C2 256
#define NK 9

typedef unsigned int u32;
typedef unsigned long long u64;

// -------- device scratch --------
__device__ float g_xp[BB * C2 * HWP];          // pointwise+BN output (16.8 MB)
__device__ float g_off[BB * 2 * NK * HWP];     // offset conv output
__device__ float g_pwt[C1 * C2];               // pw_w transposed [c][o]
__device__ float g_scale[C2];
__device__ float g_bias[C2];
// B tiles: 36 chunks x [hi|lo] x [256 o rows][72 bf16 cols] (pitch-padded, cols 0..63 valid)
__device__ __align__(128) __nv_bfloat16 g_bt[36 * 2 * 256 * 72];

// ======== SMEM layout for dcn_mma (bytes) ========
// sB: 2 bufs x (hi 36864 + lo 36864) = 147456
// sA: 2 bufs x (hi 18432 + lo 18432) = 73728
#define SM_B   0
#define SM_A   147456
#define SM_CF  221184      // wy[128], wx[128]
#define SM_CI  222208      // x0[128] x1[128] y0o[128] y1o[128]
#define SM_DYN 224256

// -------- PTX helpers (all baseline-PTX, legal on plain sm_103) --------
__device__ __forceinline__ u32 smem_u32(const void* p) {
    u32 a;
    asm("{ .reg .u64 t; cvta.to.shared.u64 t, %1; cvt.u32.u64 %0, t; }" : "=r"(a) : "l"(p));
    return a;
}
__device__ __forceinline__ void cpa16(u32 dst, const void* src) {
    asm volatile("cp.async.cg.shared.global [%0], [%1], 16;" :: "r"(dst), "l"(src));
}
__device__ __forceinline__ void cpa_commit() {
    asm volatile("cp.async.commit_group;" ::: "memory");
}
__device__ __forceinline__ void cpa_wait0() {
    asm volatile("cp.async.wait_group 0;" ::: "memory");
}
__device__ __forceinline__ void ldsm4(u32* r, u32 addr) {
    asm volatile("ldmatrix.sync.aligned.m8n8.x4.shared.b16 {%0,%1,%2,%3}, [%4];"
                 : "=r"(r[0]), "=r"(r[1]), "=r"(r[2]), "=r"(r[3]) : "r"(addr));
}
__device__ __forceinline__ void mma_bf16(float* d, const u32* a, u32 b0, u32 b1) {
    asm volatile(
        "mma.sync.aligned.m16n8k16.row.col.f32.bf16.bf16.f32 "
        "{%0,%1,%2,%3}, {%4,%5,%6,%7}, {%8,%9}, {%0,%1,%2,%3};"
        : "+f"(d[0]), "+f"(d[1]), "+f"(d[2]), "+f"(d[3])
        : "r"(a[0]), "r"(a[1]), "r"(a[2]), "r"(a[3]), "r"(b0), "r"(b1));
}
__device__ __forceinline__ u32 pack_bf2(__nv_bfloat16 a, __nv_bfloat16 b) {
    return (u32)__bfloat16_as_ushort(a) | ((u32)__bfloat16_as_ushort(b) << 16);
}

// ======================= prep kernels =======================
__global__ void prep_bn(const float* __restrict__ gamma, const float* __restrict__ beta,
                        const float* __restrict__ mean, const float* __restrict__ var) {
    int o = threadIdx.x;
    float s = gamma[o] * rsqrtf(var[o] + 1e-5f);
    g_scale[o] = s;
    g_bias[o] = beta[o] - mean[o] * s;
}

__global__ void prep_pwt(const float* __restrict__ pw) {
    int c = blockIdx.x;
    int o = threadIdx.x;
    g_pwt[c * C2 + o] = pw[o * C1 + c];
}

// chunk = n*4 + kc -> [hi|lo][o=256][72 cols], col cl holds dcn_w[o][kc*64+cl][n] split.
__global__ void prep_bt(const float* __restrict__ dcn) {
    int chunk = blockIdx.x;   // 0..35
    int n_ = chunk >> 2, kc = chunk & 3;
    int o = threadIdx.x;      // 0..255
    __nv_bfloat16* hi = g_bt + ((size_t)(chunk * 2 + 0) * 256 + o) * 72;
    __nv_bfloat16* lo = g_bt + ((size_t)(chunk * 2 + 1) * 256 + o) * 72;
#pragma unroll 4
    for (int cl = 0; cl < 64; cl++) {
        float w = dcn[(o * C2 + kc * 64 + cl) * NK + n_];
        __nv_bfloat16 h = __float2bfloat16(w);
        hi[cl] = h;
        lo[cl] = __float2bfloat16(w - __bfloat162float(h));
    }
    // padding cols (never read by ldmatrix, but keep deterministic)
    for (int cl = 64; cl < 72; cl++) { hi[cl] = __float2bfloat16(0.f); lo[cl] = __float2bfloat16(0.f); }
}

// ======================= stage 1: pointwise conv + BN =======================
__global__ void __launch_bounds__(256) pw_bn_kernel(const float* __restrict__ x) {
    __shared__ __align__(16) float sx[C1 * 16];
    __shared__ __align__(16) float spw[32 * C2];
    int t = threadIdx.x;
    int b = blockIdx.y;
    int pix0 = blockIdx.x * 16;

#pragma unroll
    for (int i = 0; i < 8; i++) {
        int j = t + i * 256;
        int c = j >> 4, p = j & 15;
        sx[j] = x[(b * C1 + c) * HWP + pix0 + p];
    }

    int obase = (t & 63) * 4;
    int pbase = (t >> 6) * 4;
    float acc[4][4];
#pragma unroll
    for (int i = 0; i < 4; i++)
#pragma unroll
        for (int j = 0; j < 4; j++) acc[i][j] = 0.f;

    for (int cc = 0; cc < C1; cc += 32) {
        __syncthreads();
#pragma unroll
        for (int i = 0; i < 32; i++) spw[i * C2 + t] = g_pwt[(cc + i) * C2 + t];
        __syncthreads();
#pragma unroll 8
        for (int c = 0; c < 32; c++) {
            float4 w4 = *(const float4*)&spw[c * C2 + obase];
            float4 x4 = *(const float4*)&sx[(cc + c) * 16 + pbase];
            acc[0][0] += w4.x * x4.x; acc[0][1] += w4.x * x4.y;
            acc[0][2] += w4.x * x4.z; acc[0][3] += w4.x * x4.w;
            acc[1][0] += w4.y * x4.x; acc[1][1] += w4.y * x4.y;
            acc[1][2] += w4.y * x4.z; acc[1][3] += w4.y * x4.w;
            acc[2][0] += w4.z * x4.x; acc[2][1] += w4.z * x4.y;
            acc[2][2] += w4.z * x4.z; acc[2][3] += w4.z * x4.w;
            acc[3][0] += w4.w * x4.x; acc[3][1] += w4.w * x4.y;
            acc[3][2] += w4.w * x4.z; acc[3][3] += w4.w * x4.w;
        }
    }
#pragma unroll
    for (int oo = 0; oo < 4; oo++) {
        int o = obase + oo;
        float s = g_scale[o], bi = g_bias[o];
#pragma unroll
        for (int pp = 0; pp < 4; pp++)
            g_xp[(b * C2 + o) * HWP + pix0 + pbase + pp] = acc[oo][pp] * s + bi;
    }
}

// ======================= stage 2: 3x3 offset conv =======================
__global__ void __launch_bounds__(288) offconv_kernel(const float* __restrict__ off_w,
                                                      const float* __restrict__ off_b) {
    __shared__ float sw[18 * 288];
    __shared__ float sx[32 * 198];
    int t = threadIdx.x;
    int b = blockIdx.y;
    int h = blockIdx.x;
    int wlo = t & 31;
    int midx = t >> 5;

    float acc00 = 0.f, acc01 = 0.f, acc10 = 0.f, acc11 = 0.f;

    for (int cc = 0; cc < C2; cc += 32) {
        __syncthreads();
#pragma unroll
        for (int m = 0; m < 18; m++)
            sw[m * 288 + t] = off_w[m * (C2 * 9) + cc * 9 + t];
        for (int j = t; j < 32 * 198; j += 288) {
            int c = j / 198;
            int r = j % 198;
            int dy = r / 66;
            int wx = (r % 66) - 1;
            int hh = h - 1 + dy;
            float v = 0.f;
            if ((unsigned)hh < 64u && (unsigned)wx < 64u)
                v = g_xp[(b * C2 + cc + c) * HWP + hh * WW + wx];
            sx[j] = v;
        }
        __syncthreads();
        for (int c = 0; c < 32; c++) {
            const float* xr = &sx[c * 198];
            const float* wa = &sw[midx * 288 + c * 9];
            const float* wb = &sw[(midx + 9) * 288 + c * 9];
#pragma unroll
            for (int dy = 0; dy < 3; dy++) {
#pragma unroll
                for (int dx = 0; dx < 3; dx++) {
                    float v0 = xr[dy * 66 + wlo + dx];
                    float v1 = xr[dy * 66 + wlo + 32 + dx];
                    float a = wa[dy * 3 + dx];
                    float bw = wb[dy * 3 + dx];
                    acc00 += a * v0;  acc01 += a * v1;
                    acc10 += bw * v0; acc11 += bw * v1;
                }
            }
        }
    }
    float ba = off_b[midx], bb2 = off_b[midx + 9];
    int base = (b * 18 + midx) * HWP + h * WW;
    g_off[base + wlo] = acc00 + ba;
    g_off[base + wlo + 32] = acc01 + ba;
    int base2 = (b * 18 + midx + 9) * HWP + h * WW;
    g_off[base2 + wlo] = acc10 + bb2;
    g_off[base2 + wlo + 32] = acc11 + bb2;
}

// ======================= stage 3: deformable sample + HMMA einsum + SiLU =======================
// Block = 128 pixels x 256 outputs, 512 threads (16 warps: 4m x 4n, warp tile m32 x n64).
// K = 2304 in 36 chunks of 64. Split bf16 (hi+lo), 3 MMA passes (hh, hl, lh).
// A: gather -> smem pitch 144B; B: pre-split global tiles via cp.async, double-buffered.
__global__ void __launch_bounds__(512, 1) dcn_mma_kernel(float* __restrict__ out) {
    extern __shared__ __align__(16) char smem[];
    u32 sb = smem_u32(smem);
    float* cf = (float*)(smem + SM_CF);
    int* ci = (int*)(smem + SM_CI);

    int t = threadIdx.x;
    int lane = t & 31;
    int warp = t >> 5;
    int rp = blockIdx.x;    // row-pair group: pixels rp*128..+127
    int b = blockIdx.y;

    int m_base = (warp & 3) * 32;
    int n_base = (warp >> 2) * 64;

    // ldmatrix lane-address offsets (A non-trans m16k16; B non-trans from [n][k] rows)
    u32 aoff = (u32)((m_base + (lane & 7) + ((lane >> 3) & 1) * 8) * 144 + (lane >> 4) * 16);
    u32 boff = (u32)((n_base + (lane & 7) + (lane >> 4) * 8) * 144 + ((lane >> 3) & 1) * 16);

    float acc[2][8][4];
#pragma unroll
    for (int i = 0; i < 2; i++)
#pragma unroll
        for (int j = 0; j < 8; j++)
#pragma unroll
            for (int r = 0; r < 4; r++) acc[i][j][r] = 0.f;

    int m = t & 127;       // pixel within block
    int kq = t >> 7;       // k-quarter (16 channels each)

    // ---- preload B chunk 0 ----
    {
        const char* src = (const char*)g_bt;
        for (int u = t; u < 4608; u += 512)
            cpa16(sb + SM_B + u * 16, src + u * 16);
        cpa_commit();
    }

    const float* xpb = g_xp + (size_t)b * C2 * HWP;

    for (int cc = 0; cc < 36; cc++) {
        int n_ = cc >> 2, kc = cc & 3;
        int abuf = cc & 1;

        if (kc == 0) {
            if (t < 128) {
                int h = rp * 2 + (t >> 6);
                int w = t & 63;
                int pix = rp * 128 + t;
                float oy = g_off[(b * 18 + n_) * HWP + pix];
                float ox = g_off[(b * 18 + n_ + 9) * HWP + pix];
                float py = (float)h + (float)(n_ / 3 - 1) + oy;
                float px = (float)w + (float)(n_ % 3 - 1) + ox;
                py = fminf(fmaxf(py, 0.f), 63.f);
                px = fminf(fmaxf(px, 0.f), 63.f);
                float y0f = floorf(py), x0f = floorf(px);
                int y0 = (int)y0f, x0 = (int)x0f;
                cf[t] = py - y0f;
                cf[128 + t] = px - x0f;
                ci[t] = x0;
                ci[128 + t] = min(x0 + 1, 63);
                ci[256 + t] = y0 * WW;
                ci[384 + t] = min(y0 + 1, 63) * WW;
            }
            __syncthreads();
        }

        // ---- gather 16 channels for pixel m (coalesced: lanes = consecutive pixels) ----
        {
            int x0 = ci[m], x1 = ci[128 + m];
            int y0o = ci[256 + m], y1o = ci[384 + m];
            float wy = cf[m], wx = cf[128 + m];
            const float* plane = xpb + (size_t)(kc * 64 + kq * 16) * HWP;
            u32 hi[8], lo[8];
#pragma unroll
            for (int j2 = 0; j2 < 8; j2++) {
                float v[2];
#pragma unroll
                for (int e = 0; e < 2; e++) {
                    const float* pl = plane + (size_t)(2 * j2 + e) * HWP;
                    float v00 = pl[y0o + x0], v01 = pl[y0o + x1];
                    float v10 = pl[y1o + x0], v11 = pl[y1o + x1];
                    float a2 = v00 + wx * (v01 - v00);
                    float b2 = v10 + wx * (v11 - v10);
                    v[e] = a2 + wy * (b2 - a2);
                }
                __nv_bfloat16 h0 = __float2bfloat16(v[0]);
                __nv_bfloat16 h1 = __float2bfloat16(v[1]);
                hi[j2] = pack_bf2(h0, h1);
                lo[j2] = pack_bf2(__float2bfloat16(v[0] - __bfloat162float(h0)),
                                  __float2bfloat16(v[1] - __bfloat162float(h1)));
            }
            char* ab = smem + SM_A + abuf * 36864 + m * 144 + kq * 32;
            *(uint4*)ab = make_uint4(hi[0], hi[1], hi[2], hi[3]);
            *(uint4*)(ab + 16) = make_uint4(hi[4], hi[5], hi[6], hi[7]);
            *(uint4*)(ab + 18432) = make_uint4(lo[0], lo[1], lo[2], lo[3]);
            *(uint4*)(ab + 18432 + 16) = make_uint4(lo[4], lo[5], lo[6], lo[7]);
        }

        cpa_wait0();          // B chunk cc resident
        __syncthreads();      // A tile + B visible to all

        if (cc < 35) {        // prefetch next B chunk into the other buffer
            const char* src = (const char*)g_bt + (size_t)(cc + 1) * 73728;
            u32 dst = sb + SM_B + (abuf ^ 1) * 73728;
            for (int u = t; u < 4608; u += 512)
                cpa16(dst + u * 16, src + u * 16);
            cpa_commit();
        }

        // ---- compute: 4 k-steps x 4 n16-groups x 2 m-tiles x 3 passes ----
        u32 sa = sb + SM_A + abuf * 36864;
        u32 sbb = sb + SM_B + abuf * 73728;
#pragma unroll
        for (int ks = 0; ks < 4; ks++) {
            u32 ah[2][4], al[2][4];
#pragma unroll
            for (int mt = 0; mt < 2; mt++) {
                ldsm4(ah[mt], sa + aoff + mt * 2304 + ks * 32);
                ldsm4(al[mt], sa + 18432 + aoff + mt * 2304 + ks * 32);
            }
#pragma unroll
            for (int ng = 0; ng < 4; ng++) {
                u32 bh[4], bl[4];
                ldsm4(bh, sbb + boff + ng * 2304 + ks * 32);
                ldsm4(bl, sbb + 36864 + boff + ng * 2304 + ks * 32);
#pragma unroll
                for (int mt = 0; mt < 2; mt++) {
                    mma_bf16(acc[mt][ng * 2 + 0], ah[mt], bh[0], bh[1]);
                    mma_bf16(acc[mt][ng * 2 + 1], ah[mt], bh[2], bh[3]);
                    mma_bf16(acc[mt][ng * 2 + 0], ah[mt], bl[0], bl[1]);
                    mma_bf16(acc[mt][ng * 2 + 1], ah[mt], bl[2], bl[3]);
                    mma_bf16(acc[mt][ng * 2 + 0], al[mt], bh[0], bh[1]);
                    mma_bf16(acc[mt][ng * 2 + 1], al[mt], bh[2], bh[3]);
                }
            }
        }
    }

    // ---- epilogue: SiLU + store ----
    float* ob = out + (size_t)b * C2 * HWP;
#pragma unroll
    for (int mt = 0; mt < 2; mt++) {
#pragma unroll
        for (int j = 0; j < 8; j++) {
#pragma unroll
            for (int r = 0; r < 4; r++) {
                int o = n_base + j * 8 + (lane & 3) * 2 + (r & 1);
                int pix = rp * 128 + m_base + mt * 16 + (lane >> 2) + (r >> 1) * 8;
                float f = acc[mt][j][r];
                f = f / (1.f + __expf(-f));
                ob[(size_t)o * HWP + pix] = f;
            }
        }
    }
}

// ======================= launch =======================
extern "C" void kernel_launch(void* const* d_in, const int* in_sizes, int n_in,
                              void* d_out, int out_size) {
    const float* x = (const float*)d_in[0];
    const float* pw_w = (const float*)d_in[1];
    const float* gamma = (const float*)d_in[2];
    const float* beta = (const float*)d_in[3];
    const float* mean = (const float*)d_in[4];
    const float* var = (const float*)d_in[5];
    const float* off_w = (const float*)d_in[6];
    const float* off_b = (const float*)d_in[7];
    const float* dcn_w = (const float*)d_in[8];
    float* out = (float*)d_out;

    (void)in_sizes; (void)n_in; (void)out_size;

    cudaFuncSetAttribute(dcn_mma_kernel, cudaFuncAttributeMaxDynamicSharedMemorySize, SM_DYN);

    prep_bn<<<1, 256>>>(gamma, beta, mean, var);
    prep_pwt<<<C1, 256>>>(pw_w);
    prep_bt<<<36, 256>>>(dcn_w);
    pw_bn_kernel<<<dim3(256, BB), 256>>>(x);
    offconv_kernel<<<dim3(HH, BB), 288>>>(off_w, off_b);
    dcn_mma_kernel<<<dim3(32, BB), 512, SM_DYN>>>(out);
}

// round 10
// speedup vs baseline: 3.3895x; 1.0018x over previous
#include <cuda_runtime.h>
#include <cuda_bf16.h>
#include <math.h>

#define HH 64
#define WW 64
#define HWP 4096
#define BB 4
#define C1 128
#define C2 256
#define NK 9

typedef unsigned int u32;
typedef unsigned long long u64;
typedef unsigned long long ull;

// -------- device scratch --------
__device__ float g_xp[BB * C2 * HWP];          // pointwise+BN output (16.8 MB)
__device__ float g_off[BB * 2 * NK * HWP];     // offset conv output
__device__ float g_pwt[C1 * C2];               // pw_w transposed [c][o]
__device__ float g_scale[C2];
__device__ float g_bias[C2];
// B tiles: 36 chunks x [hi|lo] x [256 o rows][72 bf16 cols] (pitch-padded, cols 0..63 valid)
__device__ __align__(128) __nv_bfloat16 g_bt[36 * 2 * 256 * 72];

// ======== SMEM layout for dcn_mma (bytes) ========
// sB: 2 bufs x (hi 36864 + lo 36864) = 147456
// sA: 2 bufs x (hi 18432 + lo 18432) = 73728
#define SM_B   0
#define SM_A   147456
#define SM_DYN 221184

// -------- PTX helpers (baseline PTX only; tcgen05 is sm_103a-gated and unusable) --------
__device__ __forceinline__ u32 smem_u32(const void* p) {
    u32 a;
    asm("{ .reg .u64 t; cvta.to.shared.u64 t, %1; cvt.u32.u64 %0, t; }" : "=r"(a) : "l"(p));
    return a;
}
__device__ __forceinline__ void cpa16(u32 dst, const void* src) {
    asm volatile("cp.async.cg.shared.global [%0], [%1], 16;" :: "r"(dst), "l"(src));
}
__device__ __forceinline__ void cpa_commit() {
    asm volatile("cp.async.commit_group;" ::: "memory");
}
__device__ __forceinline__ void cpa_wait1() {
    asm volatile("cp.async.wait_group 1;" ::: "memory");
}
__device__ __forceinline__ void ldsm4(u32* r, u32 addr) {
    asm volatile("ldmatrix.sync.aligned.m8n8.x4.shared.b16 {%0,%1,%2,%3}, [%4];"
                 : "=r"(r[0]), "=r"(r[1]), "=r"(r[2]), "=r"(r[3]) : "r"(addr));
}
__device__ __forceinline__ void mma_bf16(float* d, const u32* a, u32 b0, u32 b1) {
    asm volatile(
        "mma.sync.aligned.m16n8k16.row.col.f32.bf16.bf16.f32 "
        "{%0,%1,%2,%3}, {%4,%5,%6,%7}, {%8,%9}, {%0,%1,%2,%3};"
        : "+f"(d[0]), "+f"(d[1]), "+f"(d[2]), "+f"(d[3])
        : "r"(a[0]), "r"(a[1]), "r"(a[2]), "r"(a[3]), "r"(b0), "r"(b1));
}
__device__ __forceinline__ u32 cvt_bf16x2(float hi_val, float lo_val) {
    u32 r;
    asm("cvt.rn.bf16x2.f32 %0, %1, %2;" : "=r"(r) : "f"(hi_val), "f"(lo_val));
    return r;
}
// f32x2 helpers
__device__ __forceinline__ void fma2(ull& d, ull a, ull b) {
    asm("fma.rn.f32x2 %0, %1, %2, %0;" : "+l"(d) : "l"(a), "l"(b));
}
__device__ __forceinline__ ull packf2(float lo, float hi) {
    ull r;
    asm("mov.b64 %0, {%1, %2};" : "=l"(r) : "f"(lo), "f"(hi));
    return r;
}
__device__ __forceinline__ void unpackf2(float& lo, float& hi, ull v) {
    asm("mov.b64 {%0, %1}, %2;" : "=f"(lo), "=f"(hi) : "l"(v));
}

// ======================= prep kernels =======================
__global__ void prep_bn(const float* __restrict__ gamma, const float* __restrict__ beta,
                        const float* __restrict__ mean, const float* __restrict__ var) {
    int o = threadIdx.x;
    float s = gamma[o] * rsqrtf(var[o] + 1e-5f);
    g_scale[o] = s;
    g_bias[o] = beta[o] - mean[o] * s;
}

__global__ void prep_pwt(const float* __restrict__ pw) {
    int c = blockIdx.x;
    int o = threadIdx.x;
    g_pwt[c * C2 + o] = pw[o * C1 + c];
}

// chunk = n*4 + kc -> [hi|lo][o=256][72 cols], col cl holds dcn_w[o][kc*64+cl][n] split.
__global__ void prep_bt(const float* __restrict__ dcn) {
    int chunk = blockIdx.x;   // 0..35
    int n_ = chunk >> 2, kc = chunk & 3;
    int o = threadIdx.x;      // 0..255
    __nv_bfloat16* hi = g_bt + ((size_t)(chunk * 2 + 0) * 256 + o) * 72;
    __nv_bfloat16* lo = g_bt + ((size_t)(chunk * 2 + 1) * 256 + o) * 72;
#pragma unroll 4
    for (int cl = 0; cl < 64; cl++) {
        float w = dcn[(o * C2 + kc * 64 + cl) * NK + n_];
        __nv_bfloat16 h = __float2bfloat16(w);
        hi[cl] = h;
        lo[cl] = __float2bfloat16(w - __bfloat162float(h));
    }
    for (int cl = 64; cl < 72; cl++) { hi[cl] = __float2bfloat16(0.f); lo[cl] = __float2bfloat16(0.f); }
}

// ======================= stage 1: pointwise conv + BN (FFMA2) =======================
// Block = 64 pixels x 256 outputs, 256 threads. Thread tile: 8 o (4 at +0, 4 at +128)
// x 4 pixel-pairs via f32x2 FMA.
__global__ void __launch_bounds__(256) pw_bn_kernel(const float* __restrict__ x) {
    __shared__ __align__(16) float sx[C1 * 64];    // [c][64 p]  32 KB
    __shared__ __align__(16) float spw[32 * C2];   // [c][o]     32 KB
    int t = threadIdx.x;
    int b = blockIdx.y;
    int pix0 = blockIdx.x * 64;

    int og = t & 31;        // o = og*4..+3 and +128
    int pg = (t >> 5) * 4;  // first pixel-pair (0..28)

    // load x tile [128 c][64 p] (coalesced float4)
#pragma unroll
    for (int i = 0; i < 8; i++) {
        int j = t + i * 256;          // float4 index
        int c = j >> 4, p4 = (j & 15) * 4;
        *(float4*)&sx[c * 64 + p4] = *(const float4*)&x[(b * C1 + c) * HWP + pix0 + p4];
    }

    ull acc[2][4][4];
#pragma unroll
    for (int hf = 0; hf < 2; hf++)
#pragma unroll
        for (int i = 0; i < 4; i++)
#pragma unroll
            for (int j = 0; j < 4; j++) acc[hf][i][j] = 0ull;

    for (int cc = 0; cc < C1; cc += 32) {
        __syncthreads();
#pragma unroll
        for (int i = 0; i < 32; i++) spw[i * C2 + t] = g_pwt[(cc + i) * C2 + t];
        __syncthreads();
#pragma unroll 4
        for (int c = 0; c < 32; c++) {
            float4 wa = *(const float4*)&spw[c * C2 + og * 4];
            float4 wb = *(const float4*)&spw[c * C2 + 128 + og * 4];
            const float* sxr = &sx[(cc + c) * 64];
            ull s0 = *(const ull*)&sxr[(pg + 0) * 2];
            ull s1 = *(const ull*)&sxr[(pg + 1) * 2];
            ull s2 = *(const ull*)&sxr[(pg + 2) * 2];
            ull s3 = *(const ull*)&sxr[(pg + 3) * 2];
            ull w0 = packf2(wa.x, wa.x), w1 = packf2(wa.y, wa.y);
            ull w2 = packf2(wa.z, wa.z), w3 = packf2(wa.w, wa.w);
            fma2(acc[0][0][0], w0, s0); fma2(acc[0][0][1], w0, s1);
            fma2(acc[0][0][2], w0, s2); fma2(acc[0][0][3], w0, s3);
            fma2(acc[0][1][0], w1, s0); fma2(acc[0][1][1], w1, s1);
            fma2(acc[0][1][2], w1, s2); fma2(acc[0][1][3], w1, s3);
            fma2(acc[0][2][0], w2, s0); fma2(acc[0][2][1], w2, s1);
            fma2(acc[0][2][2], w2, s2); fma2(acc[0][2][3], w2, s3);
            fma2(acc[0][3][0], w3, s0); fma2(acc[0][3][1], w3, s1);
            fma2(acc[0][3][2], w3, s2); fma2(acc[0][3][3], w3, s3);
            ull w4 = packf2(wb.x, wb.x), w5 = packf2(wb.y, wb.y);
            ull w6 = packf2(wb.z, wb.z), w7 = packf2(wb.w, wb.w);
            fma2(acc[1][0][0], w4, s0); fma2(acc[1][0][1], w4, s1);
            fma2(acc[1][0][2], w4, s2); fma2(acc[1][0][3], w4, s3);
            fma2(acc[1][1][0], w5, s0); fma2(acc[1][1][1], w5, s1);
            fma2(acc[1][1][2], w5, s2); fma2(acc[1][1][3], w5, s3);
            fma2(acc[1][2][0], w6, s0); fma2(acc[1][2][1], w6, s1);
            fma2(acc[1][2][2], w6, s2); fma2(acc[1][2][3], w6, s3);
            fma2(acc[1][3][0], w7, s0); fma2(acc[1][3][1], w7, s1);
            fma2(acc[1][3][2], w7, s2); fma2(acc[1][3][3], w7, s3);
        }
    }

#pragma unroll
    for (int hf = 0; hf < 2; hf++) {
#pragma unroll
        for (int ow = 0; ow < 4; ow++) {
            int o = og * 4 + ow + hf * 128;
            float s = g_scale[o], bi = g_bias[o];
            float* orow = &g_xp[(size_t)(b * C2 + o) * HWP + pix0];
#pragma unroll
            for (int j = 0; j < 4; j++) {
                float f0, f1;
                unpackf2(f0, f1, acc[hf][ow][j]);
                int p = (pg + j) * 2;
                *(float2*)&orow[p] = make_float2(f0 * s + bi, f1 * s + bi);
            }
        }
    }
}

// ======================= stage 2: 3x3 offset conv =======================
__global__ void __launch_bounds__(288) offconv_kernel(const float* __restrict__ off_w,
                                                      const float* __restrict__ off_b) {
    __shared__ float sw[18 * 288];
    __shared__ float sx[32 * 198];
    int t = threadIdx.x;
    int b = blockIdx.y;
    int h = blockIdx.x;
    int wlo = t & 31;
    int midx = t >> 5;

    float acc00 = 0.f, acc01 = 0.f, acc10 = 0.f, acc11 = 0.f;

    for (int cc = 0; cc < C2; cc += 32) {
        __syncthreads();
#pragma unroll
        for (int m = 0; m < 18; m++)
            sw[m * 288 + t] = off_w[m * (C2 * 9) + cc * 9 + t];
        for (int j = t; j < 32 * 198; j += 288) {
            int c = j / 198;
            int r = j % 198;
            int dy = r / 66;
            int wx = (r % 66) - 1;
            int hh = h - 1 + dy;
            float v = 0.f;
            if ((unsigned)hh < 64u && (unsigned)wx < 64u)
                v = g_xp[(b * C2 + cc + c) * HWP + hh * WW + wx];
            sx[j] = v;
        }
        __syncthreads();
        for (int c = 0; c < 32; c++) {
            const float* xr = &sx[c * 198];
            const float* wa = &sw[midx * 288 + c * 9];
            const float* wb = &sw[(midx + 9) * 288 + c * 9];
#pragma unroll
            for (int dy = 0; dy < 3; dy++) {
#pragma unroll
                for (int dx = 0; dx < 3; dx++) {
                    float v0 = xr[dy * 66 + wlo + dx];
                    float v1 = xr[dy * 66 + wlo + 32 + dx];
                    float a = wa[dy * 3 + dx];
                    float bw = wb[dy * 3 + dx];
                    acc00 += a * v0;  acc01 += a * v1;
                    acc10 += bw * v0; acc11 += bw * v1;
                }
            }
        }
    }
    float ba = off_b[midx], bb2 = off_b[midx + 9];
    int base = (b * 18 + midx) * HWP + h * WW;
    g_off[base + wlo] = acc00 + ba;
    g_off[base + wlo + 32] = acc01 + ba;
    int base2 = (b * 18 + midx + 9) * HWP + h * WW;
    g_off[base2 + wlo] = acc10 + bb2;
    g_off[base2 + wlo + 32] = acc11 + bb2;
}

// ======================= stage 3: deformable sample + HMMA einsum + SiLU =======================
// Block = 128 pixels x 256 outputs, 512 threads (16 warps: 4m x 4n, warp tile m32 x n64).
// Pipeline: per chunk, gather(cc+1) is issued BEFORE compute(cc) so LDG latency and the
// fp32 convert stream overlap other warps' MMAs; one __syncthreads per chunk; coords are
// computed inline per-thread (no coords smem, no extra barrier). B double-buffered via
// cp.async with one commit per iteration (empty commit at tail keeps wait_group 1 valid).
__global__ void __launch_bounds__(512, 1) dcn_mma_kernel(float* __restrict__ out) {
    extern __shared__ __align__(16) char smem[];
    u32 sb = smem_u32(smem);

    int t = threadIdx.x;
    int lane = t & 31;
    int warp = t >> 5;
    int rp = blockIdx.x;    // pixels rp*128..+127
    int b = blockIdx.y;

    int m_base = (warp & 3) * 32;
    int n_base = (warp >> 2) * 64;

    u32 aoff = (u32)((m_base + (lane & 7) + ((lane >> 3) & 1) * 8) * 144 + (lane >> 4) * 16);
    u32 boff = (u32)((n_base + (lane & 7) + (lane >> 4) * 8) * 144 + ((lane >> 3) & 1) * 16);

    float acc[2][8][4];
#pragma unroll
    for (int i = 0; i < 2; i++)
#pragma unroll
        for (int j = 0; j < 8; j++)
#pragma unroll
            for (int r = 0; r < 4; r++) acc[i][j][r] = 0.f;

    int m = t & 127;       // pixel within block
    int kq = t >> 7;       // k-quarter (16 channels)
    int ph = m >> 6;       // pixel row parity within block
    int pw_ = m & 63;      // pixel column
    int pix = rp * 128 + m;
    int hrow = rp * 2 + ph;

    const float* xpb = g_xp + (size_t)b * C2 * HWP;
    const float* offb = g_off + (size_t)b * 18 * HWP;

    // ---- gather one chunk's worth: 16 channels for pixel m, chunk cc, into buffer abuf ----
    auto gather = [&](int cc, int abuf) {
        int n_ = cc >> 2, kc = cc & 3;
        // inline coords (per-thread, redundant across kq but barrier-free)
        float oy = offb[n_ * HWP + pix];
        float ox = offb[(n_ + 9) * HWP + pix];
        float py = (float)hrow + (float)(n_ / 3 - 1) + oy;
        float px = (float)pw_ + (float)(n_ % 3 - 1) + ox;
        py = fminf(fmaxf(py, 0.f), 63.f);
        px = fminf(fmaxf(px, 0.f), 63.f);
        float y0f = floorf(py), x0f = floorf(px);
        int y0 = (int)y0f, x0 = (int)x0f;
        int x1 = min(x0 + 1, 63);
        int y0o = y0 * WW, y1o = min(y0 + 1, 63) * WW;
        float wy = py - y0f, wx = px - x0f;
        float w00 = (1.f - wy) * (1.f - wx);
        float w01 = (1.f - wy) * wx;
        float w10 = wy * (1.f - wx);
        float w11 = wy * wx;

        const float* plane = xpb + (size_t)(kc * 64 + kq * 16) * HWP;
        u32 hi[8], lo[8];
#pragma unroll
        for (int j2 = 0; j2 < 8; j2++) {
            float v[2];
#pragma unroll
            for (int e = 0; e < 2; e++) {
                const float* pl = plane + (size_t)(2 * j2 + e) * HWP;
                v[e] = pl[y0o + x0] * w00 + pl[y0o + x1] * w01
                     + pl[y1o + x0] * w10 + pl[y1o + x1] * w11;
            }
            u32 hp = cvt_bf16x2(v[1], v[0]);   // packs {lo16=v[0], hi16=v[1]}
            hi[j2] = hp;
            float h0 = __uint_as_float(hp << 16);
            float h1 = __uint_as_float(hp & 0xffff0000u);
            lo[j2] = cvt_bf16x2(v[1] - h1, v[0] - h0);
        }
        char* ab = smem + SM_A + abuf * 36864 + m * 144 + kq * 32;
        *(uint4*)ab = make_uint4(hi[0], hi[1], hi[2], hi[3]);
        *(uint4*)(ab + 16) = make_uint4(hi[4], hi[5], hi[6], hi[7]);
        *(uint4*)(ab + 18432) = make_uint4(lo[0], lo[1], lo[2], lo[3]);
        *(uint4*)(ab + 18432 + 16) = make_uint4(lo[4], lo[5], lo[6], lo[7]);
    };

    // ---- prologue: B(0) prefetch, gather(0) ----
    {
        const char* src = (const char*)g_bt;
        for (int u = t; u < 4608; u += 512)
            cpa16(sb + SM_B + u * 16, src + u * 16);
        cpa_commit();
    }
    gather(0, 0);

    for (int cc = 0; cc < 36; cc++) {
        int abuf = cc & 1;
        __syncthreads();   // A(cc) visible; A(cc-1)/B(cc-1) consumers done

        // prefetch B(cc+1) into the other buffer (safe: its last reader was compute(cc-1))
        if (cc + 1 < 36) {
            const char* src = (const char*)g_bt + (size_t)(cc + 1) * 73728;
            u32 dst = sb + SM_B + ((cc + 1) & 1) * 73728;
            for (int u = t; u < 4608; u += 512)
                cpa16(dst + u * 16, src + u * 16);
        }
        cpa_commit();      // one group per iteration (possibly empty)

        // gather(cc+1) BEFORE compute(cc): overlaps LDG/convert with other warps' MMAs
        if (cc + 1 < 36) gather(cc + 1, abuf ^ 1);

        cpa_wait1();       // all groups except the newest done => B(cc) resident

        u32 sa = sb + SM_A + abuf * 36864;
        u32 sbb = sb + SM_B + abuf * 73728;
#pragma unroll
        for (int ks = 0; ks < 4; ks++) {
            u32 ah[2][4], al[2][4];
#pragma unroll
            for (int mt = 0; mt < 2; mt++) {
                ldsm4(ah[mt], sa + aoff + mt * 2304 + ks * 32);
                ldsm4(al[mt], sa + 18432 + aoff + mt * 2304 + ks * 32);
            }
#pragma unroll
            for (int ng = 0; ng < 4; ng++) {
                u32 bh[4], bl[4];
                ldsm4(bh, sbb + boff + ng * 2304 + ks * 32);
                ldsm4(bl, sbb + 36864 + boff + ng * 2304 + ks * 32);
#pragma unroll
                for (int mt = 0; mt < 2; mt++) {
                    mma_bf16(acc[mt][ng * 2 + 0], ah[mt], bh[0], bh[1]);
                    mma_bf16(acc[mt][ng * 2 + 1], ah[mt], bh[2], bh[3]);
                    mma_bf16(acc[mt][ng * 2 + 0], ah[mt], bl[0], bl[1]);
                    mma_bf16(acc[mt][ng * 2 + 1], ah[mt], bl[2], bl[3]);
                    mma_bf16(acc[mt][ng * 2 + 0], al[mt], bh[0], bh[1]);
                    mma_bf16(acc[mt][ng * 2 + 1], al[mt], bh[2], bh[3]);
                }
            }
        }
    }

    // ---- epilogue: SiLU + store ----
    float* ob = out + (size_t)b * C2 * HWP;
#pragma unroll
    for (int mt = 0; mt < 2; mt++) {
#pragma unroll
        for (int j = 0; j < 8; j++) {
#pragma unroll
            for (int r = 0; r < 4; r++) {
                int o = n_base + j * 8 + (lane & 3) * 2 + (r & 1);
                int opix = rp * 128 + m_base + mt * 16 + (lane >> 2) + (r >> 1) * 8;
                float f = acc[mt][j][r];
                f = f / (1.f + __expf(-f));
                ob[(size_t)o * HWP + opix] = f;
            }
        }
    }
}

// ======================= launch =======================
extern "C" void kernel_launch(void* const* d_in, const int* in_sizes, int n_in,
                              void* d_out, int out_size) {
    const float* x = (const float*)d_in[0];
    const float* pw_w = (const float*)d_in[1];
    const float* gamma = (const float*)d_in[2];
    const float* beta = (const float*)d_in[3];
    const float* mean = (const float*)d_in[4];
    const float* var = (const float*)d_in[5];
    const float* off_w = (const float*)d_in[6];
    const float* off_b = (const float*)d_in[7];
    const float* dcn_w = (const float*)d_in[8];
    float* out = (float*)d_out;

    (void)in_sizes; (void)n_in; (void)out_size;

    cudaFuncSetAttribute(dcn_mma_kernel, cudaFuncAttributeMaxDynamicSharedMemorySize, SM_DYN);

    prep_bn<<<1, 256>>>(gamma, beta, mean, var);
    prep_pwt<<<C1, 256>>>(pw_w);
    prep_bt<<<36, 256>>>(dcn_w);
    pw_bn_kernel<<<dim3(64, BB), 256>>>(x);
    offconv_kernel<<<dim3(HH, BB), 288>>>(off_w, off_b);
    dcn_mma_kernel<<<dim3(32, BB), 512, SM_DYN>>>(out);
}

// round 11
// speedup vs baseline: 4.2100x; 1.2421x over previous
#include <cuda_runtime.h>
#include <cuda_bf16.h>
#include <math.h>

#define HH 64
#define WW 64
#define HWP 4096
#define BB 4
#define C1 128
#define C2 256
#define NK 9

typedef unsigned int u32;
typedef unsigned long long u64;

// -------- device scratch --------
__device__ float g_xp[BB * C2 * HWP];          // pointwise+BN output (16.8 MB)
__device__ float g_off[BB * 2 * NK * HWP];     // offset conv output
__device__ float g_scale[C2];
__device__ float g_bias[C2];
// dcn B tiles: 36 chunks x [hi|lo] x [256 o rows][72 bf16 cols]
__device__ __align__(128) __nv_bfloat16 g_bt[36 * 2 * 256 * 72];
// pw B tiles: 2 chunks x [hi|lo] x [256 o rows][72 cols]
__device__ __align__(128) __nv_bfloat16 g_pwt2[2 * 2 * 256 * 72];
// offconv B tiles: 36 chunks x [hi|lo] x [32 rows][72 cols]
__device__ __align__(128) __nv_bfloat16 g_ow[36 * 2 * 32 * 72];

// ======== SMEM layouts (bytes) ========
// dcn: B 2x73728 | A 2x36864
#define SM_B   0
#define SM_A   147456
#define SM_DYN 221184
// pw: B 2 chunks x 73728 | A 2 bufs x 36864  (= 221184)
#define PW_B   0
#define PW_A   147456
#define PW_DYN 221184
// offconv: B 2 bufs x 9216 | A 2 bufs x 36864
#define OC_B   0
#define OC_A   18432
#define OC_DYN 92160

// -------- PTX helpers (baseline PTX only; tcgen05 is sm_103a-gated and unusable) --------
__device__ __forceinline__ u32 smem_u32(const void* p) {
    u32 a;
    asm("{ .reg .u64 t; cvta.to.shared.u64 t, %1; cvt.u32.u64 %0, t; }" : "=r"(a) : "l"(p));
    return a;
}
__device__ __forceinline__ void cpa16(u32 dst, const void* src) {
    asm volatile("cp.async.cg.shared.global [%0], [%1], 16;" :: "r"(dst), "l"(src));
}
__device__ __forceinline__ void cpa_commit() {
    asm volatile("cp.async.commit_group;" ::: "memory");
}
__device__ __forceinline__ void cpa_wait0() {
    asm volatile("cp.async.wait_group 0;" ::: "memory");
}
__device__ __forceinline__ void cpa_wait1() {
    asm volatile("cp.async.wait_group 1;" ::: "memory");
}
__device__ __forceinline__ void ldsm4(u32* r, u32 addr) {
    asm volatile("ldmatrix.sync.aligned.m8n8.x4.shared.b16 {%0,%1,%2,%3}, [%4];"
                 : "=r"(r[0]), "=r"(r[1]), "=r"(r[2]), "=r"(r[3]) : "r"(addr));
}
__device__ __forceinline__ void mma_bf16(float* d, const u32* a, u32 b0, u32 b1) {
    asm volatile(
        "mma.sync.aligned.m16n8k16.row.col.f32.bf16.bf16.f32 "
        "{%0,%1,%2,%3}, {%4,%5,%6,%7}, {%8,%9}, {%0,%1,%2,%3};"
        : "+f"(d[0]), "+f"(d[1]), "+f"(d[2]), "+f"(d[3])
        : "r"(a[0]), "r"(a[1]), "r"(a[2]), "r"(a[3]), "r"(b0), "r"(b1));
}
__device__ __forceinline__ u32 cvt_bf16x2(float hi_val, float lo_val) {
    u32 r;
    asm("cvt.rn.bf16x2.f32 %0, %1, %2;" : "=r"(r) : "f"(hi_val), "f"(lo_val));
    return r;
}
// split v0,v1 -> hi-pair and lo-pair
__device__ __forceinline__ void split2(float v0, float v1, u32& hi, u32& lo) {
    u32 hp = cvt_bf16x2(v1, v0);
    hi = hp;
    float h0 = __uint_as_float(hp << 16);
    float h1 = __uint_as_float(hp & 0xffff0000u);
    lo = cvt_bf16x2(v1 - h1, v0 - h0);
}

// ======================= prep kernels =======================
__global__ void prep_bn(const float* __restrict__ gamma, const float* __restrict__ beta,
                        const float* __restrict__ mean, const float* __restrict__ var) {
    int o = threadIdx.x;
    float s = gamma[o] * rsqrtf(var[o] + 1e-5f);
    g_scale[o] = s;
    g_bias[o] = beta[o] - mean[o] * s;
}

// pw B tiles: chunk kc -> [hi|lo][256 o][72], col cl = pw_w[o][kc*64+cl]
__global__ void prep_pwt(const float* __restrict__ pw) {
    int kc = blockIdx.x;     // 0..1
    int o = threadIdx.x;     // 0..255
    __nv_bfloat16* hi = g_pwt2 + ((size_t)(kc * 2 + 0) * 256 + o) * 72;
    __nv_bfloat16* lo = g_pwt2 + ((size_t)(kc * 2 + 1) * 256 + o) * 72;
#pragma unroll 4
    for (int cl = 0; cl < 64; cl++) {
        float w = pw[o * C1 + kc * 64 + cl];
        __nv_bfloat16 h = __float2bfloat16(w);
        hi[cl] = h;
        lo[cl] = __float2bfloat16(w - __bfloat162float(h));
    }
    for (int cl = 64; cl < 72; cl++) { hi[cl] = __float2bfloat16(0.f); lo[cl] = __float2bfloat16(0.f); }
}

// dcn B tiles: chunk = n*4+kc -> [hi|lo][256 o][72], col cl = dcn_w[o][kc*64+cl][n]
__global__ void prep_bt(const float* __restrict__ dcn) {
    int chunk = blockIdx.x;   // 0..35
    int n_ = chunk >> 2, kc = chunk & 3;
    int o = threadIdx.x;      // 0..255
    __nv_bfloat16* hi = g_bt + ((size_t)(chunk * 2 + 0) * 256 + o) * 72;
    __nv_bfloat16* lo = g_bt + ((size_t)(chunk * 2 + 1) * 256 + o) * 72;
#pragma unroll 4
    for (int cl = 0; cl < 64; cl++) {
        float w = dcn[(o * C2 + kc * 64 + cl) * NK + n_];
        __nv_bfloat16 h = __float2bfloat16(w);
        hi[cl] = h;
        lo[cl] = __float2bfloat16(w - __bfloat162float(h));
    }
    for (int cl = 64; cl < 72; cl++) { hi[cl] = __float2bfloat16(0.f); lo[cl] = __float2bfloat16(0.f); }
}

// offconv B tiles: chunk = n*4+kc -> [hi|lo][32 rows (18 used)][72], col cl = off_w[m][kc*64+cl][tap n]
__global__ void prep_ow(const float* __restrict__ off_w) {
    int chunk = blockIdx.x;   // 0..35
    int n_ = chunk >> 2, kc = chunk & 3;
    int t = threadIdx.x;      // 0..255
    int o = t & 31;
    int grp = t >> 5;         // 0..7 -> 8 cols each
    __nv_bfloat16* hi = g_ow + ((size_t)(chunk * 2 + 0) * 32 + o) * 72;
    __nv_bfloat16* lo = g_ow + ((size_t)(chunk * 2 + 1) * 32 + o) * 72;
#pragma unroll
    for (int i = 0; i < 8; i++) {
        int cl = grp * 8 + i;
        float w = (o < 18) ? off_w[(o * C2 + kc * 64 + cl) * 9 + n_] : 0.f;
        __nv_bfloat16 h = __float2bfloat16(w);
        hi[cl] = h;
        lo[cl] = __float2bfloat16(w - __bfloat162float(h));
    }
    if (grp == 0) {
        for (int cl = 64; cl < 72; cl++) { hi[cl] = __float2bfloat16(0.f); lo[cl] = __float2bfloat16(0.f); }
    }
}

// ======================= stage 1: pointwise conv + BN (HMMA) =======================
// Block = 128 pixels x 256 outputs, 512 threads (16 warps: 4m x 4n).
// K = C1 = 128 in 2 chunks of 64; B (both chunks) resident up front; A double-buffered.
__global__ void __launch_bounds__(512, 1) pw_mma_kernel(const float* __restrict__ x) {
    extern __shared__ __align__(16) char smem[];
    u32 sb = smem_u32(smem);

    int t = threadIdx.x;
    int lane = t & 31;
    int warp = t >> 5;
    int rp = blockIdx.x;    // pixels rp*128..+127
    int b = blockIdx.y;

    int m_base = (warp & 3) * 32;
    int n_base = (warp >> 2) * 64;
    u32 aoff = (u32)((m_base + (lane & 7) + ((lane >> 3) & 1) * 8) * 144 + (lane >> 4) * 16);
    u32 boff = (u32)((n_base + (lane & 7) + (lane >> 4) * 8) * 144 + ((lane >> 3) & 1) * 16);

    float acc[2][8][4];
#pragma unroll
    for (int i = 0; i < 2; i++)
#pragma unroll
        for (int j = 0; j < 8; j++)
#pragma unroll
            for (int r = 0; r < 4; r++) acc[i][j][r] = 0.f;

    int m = t & 127;
    int kq = t >> 7;
    int pix = rp * 128 + m;

    // B: load both chunks (147456 B = 9216 x 16B)
    {
        const char* src = (const char*)g_pwt2;
        for (int u = t; u < 9216; u += 512)
            cpa16(sb + PW_B + u * 16, src + u * 16);
        cpa_commit();
    }

    // A gather both chunks (registers -> smem, no barrier in between)
    const float* xb = x + (size_t)b * C1 * HWP + pix;
#pragma unroll
    for (int kc = 0; kc < 2; kc++) {
        u32 hi[8], lo[8];
#pragma unroll
        for (int j2 = 0; j2 < 8; j2++) {
            float v0 = xb[(size_t)(kc * 64 + kq * 16 + 2 * j2) * HWP];
            float v1 = xb[(size_t)(kc * 64 + kq * 16 + 2 * j2 + 1) * HWP];
            split2(v0, v1, hi[j2], lo[j2]);
        }
        char* ab = smem + PW_A + kc * 36864 + m * 144 + kq * 32;
        *(uint4*)ab = make_uint4(hi[0], hi[1], hi[2], hi[3]);
        *(uint4*)(ab + 16) = make_uint4(hi[4], hi[5], hi[6], hi[7]);
        *(uint4*)(ab + 18432) = make_uint4(lo[0], lo[1], lo[2], lo[3]);
        *(uint4*)(ab + 18432 + 16) = make_uint4(lo[4], lo[5], lo[6], lo[7]);
    }
    cpa_wait0();
    __syncthreads();

#pragma unroll
    for (int kc = 0; kc < 2; kc++) {
        u32 sa = sb + PW_A + kc * 36864;
        u32 sbb = sb + PW_B + kc * 73728;
#pragma unroll
        for (int ks = 0; ks < 4; ks++) {
            u32 ah[2][4], al[2][4];
#pragma unroll
            for (int mt = 0; mt < 2; mt++) {
                ldsm4(ah[mt], sa + aoff + mt * 2304 + ks * 32);
                ldsm4(al[mt], sa + 18432 + aoff + mt * 2304 + ks * 32);
            }
#pragma unroll
            for (int ng = 0; ng < 4; ng++) {
                u32 bh[4], bl[4];
                ldsm4(bh, sbb + boff + ng * 2304 + ks * 32);
                ldsm4(bl, sbb + 36864 + boff + ng * 2304 + ks * 32);
#pragma unroll
                for (int mt = 0; mt < 2; mt++) {
                    mma_bf16(acc[mt][ng * 2 + 0], ah[mt], bh[0], bh[1]);
                    mma_bf16(acc[mt][ng * 2 + 1], ah[mt], bh[2], bh[3]);
                    mma_bf16(acc[mt][ng * 2 + 0], ah[mt], bl[0], bl[1]);
                    mma_bf16(acc[mt][ng * 2 + 1], ah[mt], bl[2], bl[3]);
                    mma_bf16(acc[mt][ng * 2 + 0], al[mt], bh[0], bh[1]);
                    mma_bf16(acc[mt][ng * 2 + 1], al[mt], bh[2], bh[3]);
                }
            }
        }
    }

    // epilogue: BN scale/bias -> g_xp (fp32)
    float* ob = g_xp + (size_t)b * C2 * HWP;
#pragma unroll
    for (int mt = 0; mt < 2; mt++) {
#pragma unroll
        for (int j = 0; j < 8; j++) {
#pragma unroll
            for (int r = 0; r < 4; r++) {
                int o = n_base + j * 8 + (lane & 3) * 2 + (r & 1);
                int opix = rp * 128 + m_base + mt * 16 + (lane >> 2) + (r >> 1) * 8;
                ob[(size_t)o * HWP + opix] = acc[mt][j][r] * g_scale[o] + g_bias[o];
            }
        }
    }
}

// ======================= stage 2: 3x3 offset conv (HMMA) =======================
// Block = 128 pixels x 32 outputs (18 used), 512 threads (16 warps: 4m x 4n8).
// K = 2304 in 36 chunks (tap n, c-chunk kc). A = shifted xp reads (im2col), split bf16.
__global__ void __launch_bounds__(512, 1) offconv_mma_kernel(const float* __restrict__ off_b) {
    extern __shared__ __align__(16) char smem[];
    u32 sb = smem_u32(smem);

    int t = threadIdx.x;
    int lane = t & 31;
    int warp = t >> 5;
    int rp = blockIdx.x;
    int b = blockIdx.y;

    int m_base = (warp & 3) * 32;
    int n_base = (warp >> 2) * 8;
    u32 aoff = (u32)((m_base + (lane & 7) + ((lane >> 3) & 1) * 8) * 144 + (lane >> 4) * 16);
    // B ldsm n8 x k32: mats = {k0-7, k8-15, k16-23, k24-31} for rows n_base..n_base+7
    u32 boff = (u32)((n_base + (lane & 7)) * 144 + (lane >> 3) * 16);

    float acc[2][4];
#pragma unroll
    for (int i = 0; i < 2; i++)
#pragma unroll
        for (int r = 0; r < 4; r++) acc[i][r] = 0.f;

    int m = t & 127;
    int kq = t >> 7;
    int hrow = rp * 2 + (m >> 6);
    int wcol = m & 63;
    const float* xpb = g_xp + (size_t)b * C2 * HWP;

    auto gather = [&](int cc, int abuf) {
        int n_ = cc >> 2, kc = cc & 3;
        int hs = hrow + (n_ / 3 - 1);
        int ws = wcol + (n_ % 3 - 1);
        bool inb = ((unsigned)hs < 64u) && ((unsigned)ws < 64u);
        const float* src = xpb + (size_t)(kc * 64 + kq * 16) * HWP + hs * WW + ws;
        u32 hi[8], lo[8];
#pragma unroll
        for (int j2 = 0; j2 < 8; j2++) {
            float v0 = inb ? src[(size_t)(2 * j2) * HWP] : 0.f;
            float v1 = inb ? src[(size_t)(2 * j2 + 1) * HWP] : 0.f;
            split2(v0, v1, hi[j2], lo[j2]);
        }
        char* ab = smem + OC_A + abuf * 36864 + m * 144 + kq * 32;
        *(uint4*)ab = make_uint4(hi[0], hi[1], hi[2], hi[3]);
        *(uint4*)(ab + 16) = make_uint4(hi[4], hi[5], hi[6], hi[7]);
        *(uint4*)(ab + 18432) = make_uint4(lo[0], lo[1], lo[2], lo[3]);
        *(uint4*)(ab + 18432 + 16) = make_uint4(lo[4], lo[5], lo[6], lo[7]);
    };

    // prologue: B(0), gather(0)
    {
        const char* src = (const char*)g_ow;
        for (int u = t; u < 576; u += 512)
            cpa16(sb + OC_B + u * 16, src + u * 16);
        cpa_commit();
    }
    gather(0, 0);

    for (int cc = 0; cc < 36; cc++) {
        int abuf = cc & 1;
        __syncthreads();

        if (cc + 1 < 36) {
            const char* src = (const char*)g_ow + (size_t)(cc + 1) * 9216;
            u32 dst = sb + OC_B + ((cc + 1) & 1) * 9216;
            for (int u = t; u < 576; u += 512)
                cpa16(dst + u * 16, src + u * 16);
        }
        cpa_commit();
        if (cc + 1 < 36) gather(cc + 1, abuf ^ 1);
        cpa_wait1();

        u32 sa = sb + OC_A + abuf * 36864;
        u32 sbb = sb + OC_B + abuf * 9216;
#pragma unroll
        for (int kk = 0; kk < 2; kk++) {
            u32 bh[4], bl[4];
            ldsm4(bh, sbb + boff + kk * 64);
            ldsm4(bl, sbb + 4608 + boff + kk * 64);
#pragma unroll
            for (int ksh = 0; ksh < 2; ksh++) {
                int ks = kk * 2 + ksh;
                u32 ah[2][4], al[2][4];
#pragma unroll
                for (int mt = 0; mt < 2; mt++) {
                    ldsm4(ah[mt], sa + aoff + mt * 2304 + ks * 32);
                    ldsm4(al[mt], sa + 18432 + aoff + mt * 2304 + ks * 32);
                }
#pragma unroll
                for (int mt = 0; mt < 2; mt++) {
                    mma_bf16(acc[mt], ah[mt], bh[2 * ksh], bh[2 * ksh + 1]);
                    mma_bf16(acc[mt], ah[mt], bl[2 * ksh], bl[2 * ksh + 1]);
                    mma_bf16(acc[mt], al[mt], bh[2 * ksh], bh[2 * ksh + 1]);
                }
            }
        }
    }

    // epilogue: bias + store (only o < 18)
    float* ob = g_off + (size_t)b * 18 * HWP;
#pragma unroll
    for (int mt = 0; mt < 2; mt++) {
#pragma unroll
        for (int r = 0; r < 4; r++) {
            int o = n_base + (lane & 3) * 2 + (r & 1);
            int opix = rp * 128 + m_base + mt * 16 + (lane >> 2) + (r >> 1) * 8;
            if (o < 18)
                ob[(size_t)o * HWP + opix] = acc[mt][r] + off_b[o];
        }
    }
}

// ======================= stage 3: deformable sample + HMMA einsum + SiLU =======================
__global__ void __launch_bounds__(512, 1) dcn_mma_kernel(float* __restrict__ out) {
    extern __shared__ __align__(16) char smem[];
    u32 sb = smem_u32(smem);

    int t = threadIdx.x;
    int lane = t & 31;
    int warp = t >> 5;
    int rp = blockIdx.x;
    int b = blockIdx.y;

    int m_base = (warp & 3) * 32;
    int n_base = (warp >> 2) * 64;
    u32 aoff = (u32)((m_base + (lane & 7) + ((lane >> 3) & 1) * 8) * 144 + (lane >> 4) * 16);
    u32 boff = (u32)((n_base + (lane & 7) + (lane >> 4) * 8) * 144 + ((lane >> 3) & 1) * 16);

    float acc[2][8][4];
#pragma unroll
    for (int i = 0; i < 2; i++)
#pragma unroll
        for (int j = 0; j < 8; j++)
#pragma unroll
            for (int r = 0; r < 4; r++) acc[i][j][r] = 0.f;

    int m = t & 127;
    int kq = t >> 7;
    int ph = m >> 6;
    int pw_ = m & 63;
    int pix = rp * 128 + m;
    int hrow = rp * 2 + ph;

    const float* xpb = g_xp + (size_t)b * C2 * HWP;
    const float* offb = g_off + (size_t)b * 18 * HWP;

    auto gather = [&](int cc, int abuf) {
        int n_ = cc >> 2, kc = cc & 3;
        float oy = offb[n_ * HWP + pix];
        float ox = offb[(n_ + 9) * HWP + pix];
        float py = (float)hrow + (float)(n_ / 3 - 1) + oy;
        float px = (float)pw_ + (float)(n_ % 3 - 1) + ox;
        py = fminf(fmaxf(py, 0.f), 63.f);
        px = fminf(fmaxf(px, 0.f), 63.f);
        float y0f = floorf(py), x0f = floorf(px);
        int y0 = (int)y0f, x0 = (int)x0f;
        int x1 = min(x0 + 1, 63);
        int y0o = y0 * WW, y1o = min(y0 + 1, 63) * WW;
        float wy = py - y0f, wx = px - x0f;
        float w00 = (1.f - wy) * (1.f - wx);
        float w01 = (1.f - wy) * wx;
        float w10 = wy * (1.f - wx);
        float w11 = wy * wx;

        const float* plane = xpb + (size_t)(kc * 64 + kq * 16) * HWP;
        u32 hi[8], lo[8];
#pragma unroll
        for (int j2 = 0; j2 < 8; j2++) {
            float v[2];
#pragma unroll
            for (int e = 0; e < 2; e++) {
                const float* pl = plane + (size_t)(2 * j2 + e) * HWP;
                v[e] = pl[y0o + x0] * w00 + pl[y0o + x1] * w01
                     + pl[y1o + x0] * w10 + pl[y1o + x1] * w11;
            }
            split2(v[0], v[1], hi[j2], lo[j2]);
        }
        char* ab = smem + SM_A + abuf * 36864 + m * 144 + kq * 32;
        *(uint4*)ab = make_uint4(hi[0], hi[1], hi[2], hi[3]);
        *(uint4*)(ab + 16) = make_uint4(hi[4], hi[5], hi[6], hi[7]);
        *(uint4*)(ab + 18432) = make_uint4(lo[0], lo[1], lo[2], lo[3]);
        *(uint4*)(ab + 18432 + 16) = make_uint4(lo[4], lo[5], lo[6], lo[7]);
    };

    {
        const char* src = (const char*)g_bt;
        for (int u = t; u < 4608; u += 512)
            cpa16(sb + SM_B + u * 16, src + u * 16);
        cpa_commit();
    }
    gather(0, 0);

    for (int cc = 0; cc < 36; cc++) {
        int abuf = cc & 1;
        __syncthreads();

        if (cc + 1 < 36) {
            const char* src = (const char*)g_bt + (size_t)(cc + 1) * 73728;
            u32 dst = sb + SM_B + ((cc + 1) & 1) * 73728;
            for (int u = t; u < 4608; u += 512)
                cpa16(dst + u * 16, src + u * 16);
        }
        cpa_commit();
        if (cc + 1 < 36) gather(cc + 1, abuf ^ 1);
        cpa_wait1();

        u32 sa = sb + SM_A + abuf * 36864;
        u32 sbb = sb + SM_B + abuf * 73728;
#pragma unroll
        for (int ks = 0; ks < 4; ks++) {
            u32 ah[2][4], al[2][4];
#pragma unroll
            for (int mt = 0; mt < 2; mt++) {
                ldsm4(ah[mt], sa + aoff + mt * 2304 + ks * 32);
                ldsm4(al[mt], sa + 18432 + aoff + mt * 2304 + ks * 32);
            }
#pragma unroll
            for (int ng = 0; ng < 4; ng++) {
                u32 bh[4], bl[4];
                ldsm4(bh, sbb + boff + ng * 2304 + ks * 32);
                ldsm4(bl, sbb + 36864 + boff + ng * 2304 + ks * 32);
#pragma unroll
                for (int mt = 0; mt < 2; mt++) {
                    mma_bf16(acc[mt][ng * 2 + 0], ah[mt], bh[0], bh[1]);
                    mma_bf16(acc[mt][ng * 2 + 1], ah[mt], bh[2], bh[3]);
                    mma_bf16(acc[mt][ng * 2 + 0], ah[mt], bl[0], bl[1]);
                    mma_bf16(acc[mt][ng * 2 + 1], ah[mt], bl[2], bl[3]);
                    mma_bf16(acc[mt][ng * 2 + 0], al[mt], bh[0], bh[1]);
                    mma_bf16(acc[mt][ng * 2 + 1], al[mt], bh[2], bh[3]);
                }
            }
        }
    }

    float* ob = out + (size_t)b * C2 * HWP;
#pragma unroll
    for (int mt = 0; mt < 2; mt++) {
#pragma unroll
        for (int j = 0; j < 8; j++) {
#pragma unroll
            for (int r = 0; r < 4; r++) {
                int o = n_base + j * 8 + (lane & 3) * 2 + (r & 1);
                int opix = rp * 128 + m_base + mt * 16 + (lane >> 2) + (r >> 1) * 8;
                float f = acc[mt][j][r];
                f = f / (1.f + __expf(-f));
                ob[(size_t)o * HWP + opix] = f;
            }
        }
    }
}

// ======================= launch =======================
extern "C" void kernel_launch(void* const* d_in, const int* in_sizes, int n_in,
                              void* d_out, int out_size) {
    const float* x = (const float*)d_in[0];
    const float* pw_w = (const float*)d_in[1];
    const float* gamma = (const float*)d_in[2];
    const float* beta = (const float*)d_in[3];
    const float* mean = (const float*)d_in[4];
    const float* var = (const float*)d_in[5];
    const float* off_w = (const float*)d_in[6];
    const float* off_b = (const float*)d_in[7];
    const float* dcn_w = (const float*)d_in[8];
    float* out = (float*)d_out;

    (void)in_sizes; (void)n_in; (void)out_size;

    cudaFuncSetAttribute(pw_mma_kernel, cudaFuncAttributeMaxDynamicSharedMemorySize, PW_DYN);
    cudaFuncSetAttribute(offconv_mma_kernel, cudaFuncAttributeMaxDynamicSharedMemorySize, OC_DYN);
    cudaFuncSetAttribute(dcn_mma_kernel, cudaFuncAttributeMaxDynamicSharedMemorySize, SM_DYN);

    prep_bn<<<1, 256>>>(gamma, beta, mean, var);
    prep_pwt<<<2, 256>>>(pw_w);
    prep_bt<<<36, 256>>>(dcn_w);
    prep_ow<<<36, 256>>>(off_w);
    pw_mma_kernel<<<dim3(32, BB), 512, PW_DYN>>>(x);
    offconv_mma_kernel<<<dim3(32, BB), 512, OC_DYN>>>(off_b);
    dcn_mma_kernel<<<dim3(32, BB), 512, SM_DYN>>>(out);
}

// round 12
// speedup vs baseline: 5.6462x; 1.3411x over previous
#include <cuda_runtime.h>
#include <cuda_bf16.h>
#include <cuda_fp16.h>
#include <math.h>

#define HH 64
#define WW 64
#define HWP 4096
#define BB 4
#define C1 128
#define C2 256
#define NK 9

typedef unsigned int u32;
typedef unsigned long long u64;

// -------- device scratch --------
__device__ float g_xp[BB * C2 * HWP];          // pointwise+BN output (16.8 MB)
__device__ float g_off[BB * 2 * NK * HWP];     // offset conv output
__device__ float g_scale[C2];
__device__ float g_bias[C2];
// dcn B tiles (fp16, hi only): 36 chunks x [256 o rows][72 cols]
__device__ __align__(128) __half g_bt[36 * 256 * 72];
// pw B tiles (bf16 split): 2 chunks x [hi|lo] x [256 o rows][72 cols]
__device__ __align__(128) __nv_bfloat16 g_pwt2[2 * 2 * 256 * 72];
// offconv B tiles (fp16, hi only): 36 chunks x [32 rows][72 cols]
__device__ __align__(128) __half g_ow[36 * 32 * 72];

// ======== SMEM layouts (bytes) ========
// dcn: B 2 x 36864 | A 2 x (18432 hi + 18432 lo)
#define SM_B   0
#define SM_A   73728
#define SM_DYN 147456
// pw: B 2 chunks x 73728 | A 2 bufs x 36864
#define PW_B   0
#define PW_A   147456
#define PW_DYN 221184
// offconv: B 2 bufs x 4608 | A 2 bufs x 36864
#define OC_B   0
#define OC_A   9216
#define OC_DYN 82944

// -------- PTX helpers (baseline PTX only; tcgen05 is sm_103a-gated and unusable) --------
__device__ __forceinline__ u32 smem_u32(const void* p) {
    u32 a;
    asm("{ .reg .u64 t; cvta.to.shared.u64 t, %1; cvt.u32.u64 %0, t; }" : "=r"(a) : "l"(p));
    return a;
}
__device__ __forceinline__ void cpa16(u32 dst, const void* src) {
    asm volatile("cp.async.cg.shared.global [%0], [%1], 16;" :: "r"(dst), "l"(src));
}
__device__ __forceinline__ void cpa_commit() {
    asm volatile("cp.async.commit_group;" ::: "memory");
}
__device__ __forceinline__ void cpa_wait0() {
    asm volatile("cp.async.wait_group 0;" ::: "memory");
}
__device__ __forceinline__ void cpa_wait1() {
    asm volatile("cp.async.wait_group 1;" ::: "memory");
}
__device__ __forceinline__ void ldsm4(u32* r, u32 addr) {
    asm volatile("ldmatrix.sync.aligned.m8n8.x4.shared.b16 {%0,%1,%2,%3}, [%4];"
                 : "=r"(r[0]), "=r"(r[1]), "=r"(r[2]), "=r"(r[3]) : "r"(addr));
}
__device__ __forceinline__ void mma_bf16(float* d, const u32* a, u32 b0, u32 b1) {
    asm volatile(
        "mma.sync.aligned.m16n8k16.row.col.f32.bf16.bf16.f32 "
        "{%0,%1,%2,%3}, {%4,%5,%6,%7}, {%8,%9}, {%0,%1,%2,%3};"
        : "+f"(d[0]), "+f"(d[1]), "+f"(d[2]), "+f"(d[3])
        : "r"(a[0]), "r"(a[1]), "r"(a[2]), "r"(a[3]), "r"(b0), "r"(b1));
}
__device__ __forceinline__ void mma_f16(float* d, const u32* a, u32 b0, u32 b1) {
    asm volatile(
        "mma.sync.aligned.m16n8k16.row.col.f32.f16.f16.f32 "
        "{%0,%1,%2,%3}, {%4,%5,%6,%7}, {%8,%9}, {%0,%1,%2,%3};"
        : "+f"(d[0]), "+f"(d[1]), "+f"(d[2]), "+f"(d[3])
        : "r"(a[0]), "r"(a[1]), "r"(a[2]), "r"(a[3]), "r"(b0), "r"(b1));
}
__device__ __forceinline__ u32 cvt_bf16x2(float hi_val, float lo_val) {
    u32 r;
    asm("cvt.rn.bf16x2.f32 %0, %1, %2;" : "=r"(r) : "f"(hi_val), "f"(lo_val));
    return r;
}
// bf16 split (pw path)
__device__ __forceinline__ void split2(float v0, float v1, u32& hi, u32& lo) {
    u32 hp = cvt_bf16x2(v1, v0);
    hi = hp;
    float h0 = __uint_as_float(hp << 16);
    float h1 = __uint_as_float(hp & 0xffff0000u);
    lo = cvt_bf16x2(v1 - h1, v0 - h0);
}
// fp16 split (dcn/offconv path): a = ah + al exactly to ~2^-22
__device__ __forceinline__ void split2h(float v0, float v1, u32& hi, u32& lo) {
    __half2 h = __floats2half2_rn(v0, v1);
    hi = *(u32*)&h;
    float2 hf = __half22float2(h);
    __half2 l = __floats2half2_rn(v0 - hf.x, v1 - hf.y);
    lo = *(u32*)&l;
}

// ======================= fused prep kernel (single launch) =======================
// block 0..1: BN consts (block 0) + pw B chunk kc=bid (bf16 split)
// block 2..37: chunk = bid-2: dcn B tile (fp16) + offconv B tile (fp16)
__global__ void prep_all(const float* __restrict__ gamma, const float* __restrict__ beta,
                         const float* __restrict__ mean, const float* __restrict__ var,
                         const float* __restrict__ pw, const float* __restrict__ dcn,
                         const float* __restrict__ off_w) {
    int bid = blockIdx.x;
    int t = threadIdx.x;   // 0..255
    if (bid < 2) {
        if (bid == 0) {
            float s = gamma[t] * rsqrtf(var[t] + 1e-5f);
            g_scale[t] = s;
            g_bias[t] = beta[t] - mean[t] * s;
        }
        int kc = bid;
        __nv_bfloat16* hi = g_pwt2 + ((size_t)(kc * 2 + 0) * 256 + t) * 72;
        __nv_bfloat16* lo = g_pwt2 + ((size_t)(kc * 2 + 1) * 256 + t) * 72;
#pragma unroll 4
        for (int cl = 0; cl < 64; cl++) {
            float w = pw[t * C1 + kc * 64 + cl];
            __nv_bfloat16 h = __float2bfloat16(w);
            hi[cl] = h;
            lo[cl] = __float2bfloat16(w - __bfloat162float(h));
        }
        for (int cl = 64; cl < 72; cl++) { hi[cl] = __float2bfloat16(0.f); lo[cl] = __float2bfloat16(0.f); }
    } else {
        int chunk = bid - 2;            // 0..35
        int n_ = chunk >> 2, kc = chunk & 3;
        // dcn B tile (fp16 rounded)
        __half* bt = g_bt + ((size_t)chunk * 256 + t) * 72;
#pragma unroll 4
        for (int cl = 0; cl < 64; cl++)
            bt[cl] = __float2half_rn(dcn[(t * C2 + kc * 64 + cl) * NK + n_]);
        for (int cl = 64; cl < 72; cl++) bt[cl] = __float2half_rn(0.f);
        // offconv B tile (fp16 rounded): rows 32 (18 used), 8 threads per row
        {
            int o = t & 31;
            int grp = t >> 5;
            __half* ow = g_ow + ((size_t)chunk * 32 + o) * 72;
#pragma unroll
            for (int i = 0; i < 8; i++) {
                int cl = grp * 8 + i;
                float w = (o < 18) ? off_w[(o * C2 + kc * 64 + cl) * 9 + n_] : 0.f;
                ow[cl] = __float2half_rn(w);
            }
            if (grp == 0)
                for (int cl = 64; cl < 72; cl++) ow[cl] = __float2half_rn(0.f);
        }
    }
}

// ======================= stage 1: pointwise conv + BN (HMMA bf16 3-pass) =======================
__global__ void __launch_bounds__(512, 1) pw_mma_kernel(const float* __restrict__ x) {
    extern __shared__ __align__(16) char smem[];
    u32 sb = smem_u32(smem);

    int t = threadIdx.x;
    int lane = t & 31;
    int warp = t >> 5;
    int rp = blockIdx.x;
    int b = blockIdx.y;

    int m_base = (warp & 3) * 32;
    int n_base = (warp >> 2) * 64;
    u32 aoff = (u32)((m_base + (lane & 7) + ((lane >> 3) & 1) * 8) * 144 + (lane >> 4) * 16);
    u32 boff = (u32)((n_base + (lane & 7) + (lane >> 4) * 8) * 144 + ((lane >> 3) & 1) * 16);

    float acc[2][8][4];
#pragma unroll
    for (int i = 0; i < 2; i++)
#pragma unroll
        for (int j = 0; j < 8; j++)
#pragma unroll
            for (int r = 0; r < 4; r++) acc[i][j][r] = 0.f;

    int m = t & 127;
    int kq = t >> 7;
    int pix = rp * 128 + m;

    {
        const char* src = (const char*)g_pwt2;
        for (int u = t; u < 9216; u += 512)
            cpa16(sb + PW_B + u * 16, src + u * 16);
        cpa_commit();
    }

    const float* xb = x + (size_t)b * C1 * HWP + pix;
#pragma unroll
    for (int kc = 0; kc < 2; kc++) {
        u32 hi[8], lo[8];
#pragma unroll
        for (int j2 = 0; j2 < 8; j2++) {
            float v0 = xb[(size_t)(kc * 64 + kq * 16 + 2 * j2) * HWP];
            float v1 = xb[(size_t)(kc * 64 + kq * 16 + 2 * j2 + 1) * HWP];
            split2(v0, v1, hi[j2], lo[j2]);
        }
        char* ab = smem + PW_A + kc * 36864 + m * 144 + kq * 32;
        *(uint4*)ab = make_uint4(hi[0], hi[1], hi[2], hi[3]);
        *(uint4*)(ab + 16) = make_uint4(hi[4], hi[5], hi[6], hi[7]);
        *(uint4*)(ab + 18432) = make_uint4(lo[0], lo[1], lo[2], lo[3]);
        *(uint4*)(ab + 18432 + 16) = make_uint4(lo[4], lo[5], lo[6], lo[7]);
    }
    cpa_wait0();
    __syncthreads();

#pragma unroll
    for (int kc = 0; kc < 2; kc++) {
        u32 sa = sb + PW_A + kc * 36864;
        u32 sbb = sb + PW_B + kc * 73728;
#pragma unroll
        for (int ks = 0; ks < 4; ks++) {
            u32 ah[2][4], al[2][4];
#pragma unroll
            for (int mt = 0; mt < 2; mt++) {
                ldsm4(ah[mt], sa + aoff + mt * 2304 + ks * 32);
                ldsm4(al[mt], sa + 18432 + aoff + mt * 2304 + ks * 32);
            }
#pragma unroll
            for (int ng = 0; ng < 4; ng++) {
                u32 bh[4], bl[4];
                ldsm4(bh, sbb + boff + ng * 2304 + ks * 32);
                ldsm4(bl, sbb + 36864 + boff + ng * 2304 + ks * 32);
#pragma unroll
                for (int mt = 0; mt < 2; mt++) {
                    mma_bf16(acc[mt][ng * 2 + 0], ah[mt], bh[0], bh[1]);
                    mma_bf16(acc[mt][ng * 2 + 1], ah[mt], bh[2], bh[3]);
                    mma_bf16(acc[mt][ng * 2 + 0], ah[mt], bl[0], bl[1]);
                    mma_bf16(acc[mt][ng * 2 + 1], ah[mt], bl[2], bl[3]);
                    mma_bf16(acc[mt][ng * 2 + 0], al[mt], bh[0], bh[1]);
                    mma_bf16(acc[mt][ng * 2 + 1], al[mt], bh[2], bh[3]);
                }
            }
        }
    }

    float* ob = g_xp + (size_t)b * C2 * HWP;
#pragma unroll
    for (int mt = 0; mt < 2; mt++) {
#pragma unroll
        for (int j = 0; j < 8; j++) {
#pragma unroll
            for (int r = 0; r < 4; r++) {
                int o = n_base + j * 8 + (lane & 3) * 2 + (r & 1);
                int opix = rp * 128 + m_base + mt * 16 + (lane >> 2) + (r >> 1) * 8;
                ob[(size_t)o * HWP + opix] = acc[mt][j][r] * g_scale[o] + g_bias[o];
            }
        }
    }
}

// ======================= stage 2: 3x3 offset conv (HMMA fp16 2-pass) =======================
__global__ void __launch_bounds__(512, 1) offconv_mma_kernel(const float* __restrict__ off_b) {
    extern __shared__ __align__(16) char smem[];
    u32 sb = smem_u32(smem);

    int t = threadIdx.x;
    int lane = t & 31;
    int warp = t >> 5;
    int rp = blockIdx.x;
    int b = blockIdx.y;

    int m_base = (warp & 3) * 32;
    int n_base = (warp >> 2) * 8;
    u32 aoff = (u32)((m_base + (lane & 7) + ((lane >> 3) & 1) * 8) * 144 + (lane >> 4) * 16);
    u32 boff = (u32)((n_base + (lane & 7)) * 144 + (lane >> 3) * 16);

    float acc[2][4];
#pragma unroll
    for (int i = 0; i < 2; i++)
#pragma unroll
        for (int r = 0; r < 4; r++) acc[i][r] = 0.f;

    int m = t & 127;
    int kq = t >> 7;
    int hrow = rp * 2 + (m >> 6);
    int wcol = m & 63;
    const float* xpb = g_xp + (size_t)b * C2 * HWP;

    auto gather = [&](int cc, int abuf) {
        int n_ = cc >> 2, kc = cc & 3;
        int hs = hrow + (n_ / 3 - 1);
        int ws = wcol + (n_ % 3 - 1);
        bool inb = ((unsigned)hs < 64u) && ((unsigned)ws < 64u);
        const float* src = xpb + (size_t)(kc * 64 + kq * 16) * HWP + hs * WW + ws;
        u32 hi[8], lo[8];
#pragma unroll
        for (int j2 = 0; j2 < 8; j2++) {
            float v0 = inb ? src[(size_t)(2 * j2) * HWP] : 0.f;
            float v1 = inb ? src[(size_t)(2 * j2 + 1) * HWP] : 0.f;
            split2h(v0, v1, hi[j2], lo[j2]);
        }
        char* ab = smem + OC_A + abuf * 36864 + m * 144 + kq * 32;
        *(uint4*)ab = make_uint4(hi[0], hi[1], hi[2], hi[3]);
        *(uint4*)(ab + 16) = make_uint4(hi[4], hi[5], hi[6], hi[7]);
        *(uint4*)(ab + 18432) = make_uint4(lo[0], lo[1], lo[2], lo[3]);
        *(uint4*)(ab + 18432 + 16) = make_uint4(lo[4], lo[5], lo[6], lo[7]);
    };

    {
        const char* src = (const char*)g_ow;
        for (int u = t; u < 288; u += 512)
            if (u < 288) cpa16(sb + OC_B + u * 16, src + u * 16);
        cpa_commit();
    }
    gather(0, 0);

    for (int cc = 0; cc < 36; cc++) {
        int abuf = cc & 1;
        __syncthreads();

        if (cc + 1 < 36) {
            const char* src = (const char*)g_ow + (size_t)(cc + 1) * 4608;
            u32 dst = sb + OC_B + ((cc + 1) & 1) * 4608;
            for (int u = t; u < 288; u += 512)
                if (u < 288) cpa16(dst + u * 16, src + u * 16);
        }
        cpa_commit();
        if (cc + 1 < 36) gather(cc + 1, abuf ^ 1);
        cpa_wait1();

        u32 sa = sb + OC_A + abuf * 36864;
        u32 sbb = sb + OC_B + abuf * 4608;
#pragma unroll
        for (int kk = 0; kk < 2; kk++) {
            u32 bh[4];
            ldsm4(bh, sbb + boff + kk * 64);
#pragma unroll
            for (int ksh = 0; ksh < 2; ksh++) {
                int ks = kk * 2 + ksh;
                u32 ah[2][4], al[2][4];
#pragma unroll
                for (int mt = 0; mt < 2; mt++) {
                    ldsm4(ah[mt], sa + aoff + mt * 2304 + ks * 32);
                    ldsm4(al[mt], sa + 18432 + aoff + mt * 2304 + ks * 32);
                }
#pragma unroll
                for (int mt = 0; mt < 2; mt++) {
                    mma_f16(acc[mt], ah[mt], bh[2 * ksh], bh[2 * ksh + 1]);
                    mma_f16(acc[mt], al[mt], bh[2 * ksh], bh[2 * ksh + 1]);
                }
            }
        }
    }

    float* ob = g_off + (size_t)b * 18 * HWP;
#pragma unroll
    for (int mt = 0; mt < 2; mt++) {
#pragma unroll
        for (int r = 0; r < 4; r++) {
            int o = n_base + (lane & 3) * 2 + (r & 1);
            int opix = rp * 128 + m_base + mt * 16 + (lane >> 2) + (r >> 1) * 8;
            if (o < 18)
                ob[(size_t)o * HWP + opix] = acc[mt][r] + off_b[o];
        }
    }
}

// ======================= stage 3: deformable sample + HMMA fp16 2-pass + SiLU =======================
__global__ void __launch_bounds__(512, 1) dcn_mma_kernel(float* __restrict__ out) {
    extern __shared__ __align__(16) char smem[];
    u32 sb = smem_u32(smem);

    int t = threadIdx.x;
    int lane = t & 31;
    int warp = t >> 5;
    int rp = blockIdx.x;
    int b = blockIdx.y;

    int m_base = (warp & 3) * 32;
    int n_base = (warp >> 2) * 64;
    u32 aoff = (u32)((m_base + (lane & 7) + ((lane >> 3) & 1) * 8) * 144 + (lane >> 4) * 16);
    u32 boff = (u32)((n_base + (lane & 7) + (lane >> 4) * 8) * 144 + ((lane >> 3) & 1) * 16);

    float acc[2][8][4];
#pragma unroll
    for (int i = 0; i < 2; i++)
#pragma unroll
        for (int j = 0; j < 8; j++)
#pragma unroll
            for (int r = 0; r < 4; r++) acc[i][j][r] = 0.f;

    int m = t & 127;
    int kq = t >> 7;
    int ph = m >> 6;
    int pw_ = m & 63;
    int pix = rp * 128 + m;
    int hrow = rp * 2 + ph;

    const float* xpb = g_xp + (size_t)b * C2 * HWP;
    const float* offb = g_off + (size_t)b * 18 * HWP;

    auto gather = [&](int cc, int abuf) {
        int n_ = cc >> 2, kc = cc & 3;
        float oy = offb[n_ * HWP + pix];
        float ox = offb[(n_ + 9) * HWP + pix];
        float py = (float)hrow + (float)(n_ / 3 - 1) + oy;
        float px = (float)pw_ + (float)(n_ % 3 - 1) + ox;
        py = fminf(fmaxf(py, 0.f), 63.f);
        px = fminf(fmaxf(px, 0.f), 63.f);
        float y0f = floorf(py), x0f = floorf(px);
        int y0 = (int)y0f, x0 = (int)x0f;
        int x1 = min(x0 + 1, 63);
        int y0o = y0 * WW, y1o = min(y0 + 1, 63) * WW;
        float wy = py - y0f, wx = px - x0f;
        float w00 = (1.f - wy) * (1.f - wx);
        float w01 = (1.f - wy) * wx;
        float w10 = wy * (1.f - wx);
        float w11 = wy * wx;

        const float* plane = xpb + (size_t)(kc * 64 + kq * 16) * HWP;
        u32 hi[8], lo[8];
#pragma unroll
        for (int j2 = 0; j2 < 8; j2++) {
            float v[2];
#pragma unroll
            for (int e = 0; e < 2; e++) {
                const float* pl = plane + (size_t)(2 * j2 + e) * HWP;
                v[e] = pl[y0o + x0] * w00 + pl[y0o + x1] * w01
                     + pl[y1o + x0] * w10 + pl[y1o + x1] * w11;
            }
            split2h(v[0], v[1], hi[j2], lo[j2]);
        }
        char* ab = smem + SM_A + abuf * 36864 + m * 144 + kq * 32;
        *(uint4*)ab = make_uint4(hi[0], hi[1], hi[2], hi[3]);
        *(uint4*)(ab + 16) = make_uint4(hi[4], hi[5], hi[6], hi[7]);
        *(uint4*)(ab + 18432) = make_uint4(lo[0], lo[1], lo[2], lo[3]);
        *(uint4*)(ab + 18432 + 16) = make_uint4(lo[4], lo[5], lo[6], lo[7]);
    };

    {
        const char* src = (const char*)g_bt;
        for (int u = t; u < 2304; u += 512)
            cpa16(sb + SM_B + u * 16, src + u * 16);
        cpa_commit();
    }
    gather(0, 0);

    for (int cc = 0; cc < 36; cc++) {
        int abuf = cc & 1;
        __syncthreads();

        if (cc + 1 < 36) {
            const char* src = (const char*)g_bt + (size_t)(cc + 1) * 36864;
            u32 dst = sb + SM_B + ((cc + 1) & 1) * 36864;
            for (int u = t; u < 2304; u += 512)
                cpa16(dst + u * 16, src + u * 16);
        }
        cpa_commit();
        if (cc + 1 < 36) gather(cc + 1, abuf ^ 1);
        cpa_wait1();

        u32 sa = sb + SM_A + abuf * 36864;
        u32 sbb = sb + SM_B + abuf * 36864;
#pragma unroll
        for (int ks = 0; ks < 4; ks++) {
            u32 ah[2][4], al[2][4];
#pragma unroll
            for (int mt = 0; mt < 2; mt++) {
                ldsm4(ah[mt], sa + aoff + mt * 2304 + ks * 32);
                ldsm4(al[mt], sa + 18432 + aoff + mt * 2304 + ks * 32);
            }
#pragma unroll
            for (int ng = 0; ng < 4; ng++) {
                u32 bh[4];
                ldsm4(bh, sbb + boff + ng * 2304 + ks * 32);
#pragma unroll
                for (int mt = 0; mt < 2; mt++) {
                    mma_f16(acc[mt][ng * 2 + 0], ah[mt], bh[0], bh[1]);
                    mma_f16(acc[mt][ng * 2 + 1], ah[mt], bh[2], bh[3]);
                    mma_f16(acc[mt][ng * 2 + 0], al[mt], bh[0], bh[1]);
                    mma_f16(acc[mt][ng * 2 + 1], al[mt], bh[2], bh[3]);
                }
            }
        }
    }

    float* ob = out + (size_t)b * C2 * HWP;
#pragma unroll
    for (int mt = 0; mt < 2; mt++) {
#pragma unroll
        for (int j = 0; j < 8; j++) {
#pragma unroll
            for (int r = 0; r < 4; r++) {
                int o = n_base + j * 8 + (lane & 3) * 2 + (r & 1);
                int opix = rp * 128 + m_base + mt * 16 + (lane >> 2) + (r >> 1) * 8;
                float f = acc[mt][j][r];
                f = f / (1.f + __expf(-f));
                ob[(size_t)o * HWP + opix] = f;
            }
        }
    }
}

// ======================= launch =======================
extern "C" void kernel_launch(void* const* d_in, const int* in_sizes, int n_in,
                              void* d_out, int out_size) {
    const float* x = (const float*)d_in[0];
    const float* pw_w = (const float*)d_in[1];
    const float* gamma = (const float*)d_in[2];
    const float* beta = (const float*)d_in[3];
    const float* mean = (const float*)d_in[4];
    const float* var = (const float*)d_in[5];
    const float* off_w = (const float*)d_in[6];
    const float* off_b = (const float*)d_in[7];
    const float* dcn_w = (const float*)d_in[8];
    float* out = (float*)d_out;

    (void)in_sizes; (void)n_in; (void)out_size;

    cudaFuncSetAttribute(pw_mma_kernel, cudaFuncAttributeMaxDynamicSharedMemorySize, PW_DYN);
    cudaFuncSetAttribute(offconv_mma_kernel, cudaFuncAttributeMaxDynamicSharedMemorySize, OC_DYN);
    cudaFuncSetAttribute(dcn_mma_kernel, cudaFuncAttributeMaxDynamicSharedMemorySize, SM_DYN);

    prep_all<<<38, 256>>>(gamma, beta, mean, var, pw_w, dcn_w, off_w);
    pw_mma_kernel<<<dim3(32, BB), 512, PW_DYN>>>(x);
    offconv_mma_kernel<<<dim3(32, BB), 512, OC_DYN>>>(off_b);
    dcn_mma_kernel<<<dim3(32, BB), 512, SM_DYN>>>(out);
}

// round 13
// speedup vs baseline: 6.1972x; 1.0976x over previous
#include <cuda_runtime.h>
#include <cuda_bf16.h>
#include <cuda_fp16.h>
#include <math.h>

#define HH 64
#define WW 64
#define HWP 4096
#define BB 4
#define C1 128
#define C2 256
#define NK 9

typedef unsigned int u32;
typedef unsigned long long u64;

// -------- device scratch --------
__device__ float g_xp[BB * C2 * HWP];          // pointwise+BN output (16.8 MB)
__device__ float g_off[BB * 2 * NK * HWP];     // offset conv output
__device__ float g_scale[C2];
__device__ float g_bias[C2];
// dcn B tiles (fp16, hi only): 36 chunks x [256 o rows][72 cols]
__device__ __align__(128) __half g_bt[36 * 256 * 72];
// pw B tiles (bf16 split): 2 chunks x [hi|lo] x [256 o rows][72 cols]
__device__ __align__(128) __nv_bfloat16 g_pwt2[2 * 2 * 256 * 72];
// offconv B tiles (fp16, hi only): 36 chunks x [32 rows][72 cols]
__device__ __align__(128) __half g_ow[36 * 32 * 72];

// ======== SMEM layouts (bytes) ========
// dcn: B 2 x 36864 | A 2 x (18432 hi + 18432 lo)
#define SM_B   0
#define SM_A   73728
#define SM_DYN 147456
// pw: B 2 chunks x 73728 | A 2 bufs x 36864
#define PW_B   0
#define PW_A   147456
#define PW_DYN 221184
// offconv: B 2 bufs x 4608 | A 2 bufs x 36864
#define OC_B   0
#define OC_A   9216
#define OC_DYN 82944

// -------- PTX helpers (baseline PTX only; tcgen05 is sm_103a-gated and unusable) --------
__device__ __forceinline__ u32 smem_u32(const void* p) {
    u32 a;
    asm("{ .reg .u64 t; cvta.to.shared.u64 t, %1; cvt.u32.u64 %0, t; }" : "=r"(a) : "l"(p));
    return a;
}
__device__ __forceinline__ void cpa16(u32 dst, const void* src) {
    asm volatile("cp.async.cg.shared.global [%0], [%1], 16;" :: "r"(dst), "l"(src));
}
__device__ __forceinline__ void cpa_commit() {
    asm volatile("cp.async.commit_group;" ::: "memory");
}
__device__ __forceinline__ void cpa_wait0() {
    asm volatile("cp.async.wait_group 0;" ::: "memory");
}
__device__ __forceinline__ void cpa_wait1() {
    asm volatile("cp.async.wait_group 1;" ::: "memory");
}
__device__ __forceinline__ void ldsm4(u32* r, u32 addr) {
    asm volatile("ldmatrix.sync.aligned.m8n8.x4.shared.b16 {%0,%1,%2,%3}, [%4];"
                 : "=r"(r[0]), "=r"(r[1]), "=r"(r[2]), "=r"(r[3]) : "r"(addr));
}
__device__ __forceinline__ void mma_bf16(float* d, const u32* a, u32 b0, u32 b1) {
    asm volatile(
        "mma.sync.aligned.m16n8k16.row.col.f32.bf16.bf16.f32 "
        "{%0,%1,%2,%3}, {%4,%5,%6,%7}, {%8,%9}, {%0,%1,%2,%3};"
        : "+f"(d[0]), "+f"(d[1]), "+f"(d[2]), "+f"(d[3])
        : "r"(a[0]), "r"(a[1]), "r"(a[2]), "r"(a[3]), "r"(b0), "r"(b1));
}
__device__ __forceinline__ void mma_f16(float* d, const u32* a, u32 b0, u32 b1) {
    asm volatile(
        "mma.sync.aligned.m16n8k16.row.col.f32.f16.f16.f32 "
        "{%0,%1,%2,%3}, {%4,%5,%6,%7}, {%8,%9}, {%0,%1,%2,%3};"
        : "+f"(d[0]), "+f"(d[1]), "+f"(d[2]), "+f"(d[3])
        : "r"(a[0]), "r"(a[1]), "r"(a[2]), "r"(a[3]), "r"(b0), "r"(b1));
}
__device__ __forceinline__ u32 cvt_bf16x2(float hi_val, float lo_val) {
    u32 r;
    asm("cvt.rn.bf16x2.f32 %0, %1, %2;" : "=r"(r) : "f"(hi_val), "f"(lo_val));
    return r;
}
// bf16 split (pw path)
__device__ __forceinline__ void split2(float v0, float v1, u32& hi, u32& lo) {
    u32 hp = cvt_bf16x2(v1, v0);
    hi = hp;
    float h0 = __uint_as_float(hp << 16);
    float h1 = __uint_as_float(hp & 0xffff0000u);
    lo = cvt_bf16x2(v1 - h1, v0 - h0);
}
// fp16 split (dcn/offconv path): a = ah + al exactly to ~2^-22
__device__ __forceinline__ void split2h(float v0, float v1, u32& hi, u32& lo) {
    __half2 h = __floats2half2_rn(v0, v1);
    hi = *(u32*)&h;
    float2 hf = __half22float2(h);
    __half2 l = __floats2half2_rn(v0 - hf.x, v1 - hf.y);
    lo = *(u32*)&l;
}

// ======================= fused prep kernel (single launch) =======================
__global__ void prep_all(const float* __restrict__ gamma, const float* __restrict__ beta,
                         const float* __restrict__ mean, const float* __restrict__ var,
                         const float* __restrict__ pw, const float* __restrict__ dcn,
                         const float* __restrict__ off_w) {
    int bid = blockIdx.x;
    int t = threadIdx.x;   // 0..255
    if (bid < 2) {
        if (bid == 0) {
            float s = gamma[t] * rsqrtf(var[t] + 1e-5f);
            g_scale[t] = s;
            g_bias[t] = beta[t] - mean[t] * s;
        }
        int kc = bid;
        __nv_bfloat16* hi = g_pwt2 + ((size_t)(kc * 2 + 0) * 256 + t) * 72;
        __nv_bfloat16* lo = g_pwt2 + ((size_t)(kc * 2 + 1) * 256 + t) * 72;
#pragma unroll 4
        for (int cl = 0; cl < 64; cl++) {
            float w = pw[t * C1 + kc * 64 + cl];
            __nv_bfloat16 h = __float2bfloat16(w);
            hi[cl] = h;
            lo[cl] = __float2bfloat16(w - __bfloat162float(h));
        }
        for (int cl = 64; cl < 72; cl++) { hi[cl] = __float2bfloat16(0.f); lo[cl] = __float2bfloat16(0.f); }
    } else {
        int chunk = bid - 2;            // 0..35
        int n_ = chunk >> 2, kc = chunk & 3;
        __half* bt = g_bt + ((size_t)chunk * 256 + t) * 72;
#pragma unroll 4
        for (int cl = 0; cl < 64; cl++)
            bt[cl] = __float2half_rn(dcn[(t * C2 + kc * 64 + cl) * NK + n_]);
        for (int cl = 64; cl < 72; cl++) bt[cl] = __float2half_rn(0.f);
        {
            int o = t & 31;
            int grp = t >> 5;
            __half* ow = g_ow + ((size_t)chunk * 32 + o) * 72;
#pragma unroll
            for (int i = 0; i < 8; i++) {
                int cl = grp * 8 + i;
                float w = (o < 18) ? off_w[(o * C2 + kc * 64 + cl) * 9 + n_] : 0.f;
                ow[cl] = __float2half_rn(w);
            }
            if (grp == 0)
                for (int cl = 64; cl < 72; cl++) ow[cl] = __float2half_rn(0.f);
        }
    }
}

// ======================= stage 1: pointwise conv + BN (HMMA bf16 3-pass) =======================
__global__ void __launch_bounds__(512, 1) pw_mma_kernel(const float* __restrict__ x) {
    extern __shared__ __align__(16) char smem[];
    u32 sb = smem_u32(smem);

    int t = threadIdx.x;
    int lane = t & 31;
    int warp = t >> 5;
    int rp = blockIdx.x;
    int b = blockIdx.y;

    int m_base = (warp & 3) * 32;
    int n_base = (warp >> 2) * 64;
    u32 aoff = (u32)((m_base + (lane & 7) + ((lane >> 3) & 1) * 8) * 144 + (lane >> 4) * 16);
    u32 boff = (u32)((n_base + (lane & 7) + (lane >> 4) * 8) * 144 + ((lane >> 3) & 1) * 16);

    float acc[2][8][4];
#pragma unroll
    for (int i = 0; i < 2; i++)
#pragma unroll
        for (int j = 0; j < 8; j++)
#pragma unroll
            for (int r = 0; r < 4; r++) acc[i][j][r] = 0.f;

    int m = t & 127;
    int kq = t >> 7;
    int pix = rp * 128 + m;

    {
        const char* src = (const char*)g_pwt2;
        for (int u = t; u < 9216; u += 512)
            cpa16(sb + PW_B + u * 16, src + u * 16);
        cpa_commit();
    }

    const float* xb = x + (size_t)b * C1 * HWP + pix;
#pragma unroll
    for (int kc = 0; kc < 2; kc++) {
        u32 hi[8], lo[8];
#pragma unroll
        for (int j2 = 0; j2 < 8; j2++) {
            float v0 = xb[(size_t)(kc * 64 + kq * 16 + 2 * j2) * HWP];
            float v1 = xb[(size_t)(kc * 64 + kq * 16 + 2 * j2 + 1) * HWP];
            split2(v0, v1, hi[j2], lo[j2]);
        }
        char* ab = smem + PW_A + kc * 36864 + m * 144 + kq * 32;
        *(uint4*)ab = make_uint4(hi[0], hi[1], hi[2], hi[3]);
        *(uint4*)(ab + 16) = make_uint4(hi[4], hi[5], hi[6], hi[7]);
        *(uint4*)(ab + 18432) = make_uint4(lo[0], lo[1], lo[2], lo[3]);
        *(uint4*)(ab + 18432 + 16) = make_uint4(lo[4], lo[5], lo[6], lo[7]);
    }
    cpa_wait0();
    __syncthreads();

#pragma unroll
    for (int kc = 0; kc < 2; kc++) {
        u32 sa = sb + PW_A + kc * 36864;
        u32 sbb = sb + PW_B + kc * 73728;
#pragma unroll
        for (int ks = 0; ks < 4; ks++) {
            u32 ah[2][4], al[2][4];
#pragma unroll
            for (int mt = 0; mt < 2; mt++) {
                ldsm4(ah[mt], sa + aoff + mt * 2304 + ks * 32);
                ldsm4(al[mt], sa + 18432 + aoff + mt * 2304 + ks * 32);
            }
#pragma unroll
            for (int ng = 0; ng < 4; ng++) {
                u32 bh[4], bl[4];
                ldsm4(bh, sbb + boff + ng * 2304 + ks * 32);
                ldsm4(bl, sbb + 36864 + boff + ng * 2304 + ks * 32);
#pragma unroll
                for (int mt = 0; mt < 2; mt++) {
                    mma_bf16(acc[mt][ng * 2 + 0], ah[mt], bh[0], bh[1]);
                    mma_bf16(acc[mt][ng * 2 + 1], ah[mt], bh[2], bh[3]);
                    mma_bf16(acc[mt][ng * 2 + 0], ah[mt], bl[0], bl[1]);
                    mma_bf16(acc[mt][ng * 2 + 1], ah[mt], bl[2], bl[3]);
                    mma_bf16(acc[mt][ng * 2 + 0], al[mt], bh[0], bh[1]);
                    mma_bf16(acc[mt][ng * 2 + 1], al[mt], bh[2], bh[3]);
                }
            }
        }
    }

    float* ob = g_xp + (size_t)b * C2 * HWP;
#pragma unroll
    for (int mt = 0; mt < 2; mt++) {
#pragma unroll
        for (int j = 0; j < 8; j++) {
#pragma unroll
            for (int r = 0; r < 4; r++) {
                int o = n_base + j * 8 + (lane & 3) * 2 + (r & 1);
                int opix = rp * 128 + m_base + mt * 16 + (lane >> 2) + (r >> 1) * 8;
                ob[(size_t)o * HWP + opix] = acc[mt][j][r] * g_scale[o] + g_bias[o];
            }
        }
    }
}

// ======================= stage 2: 3x3 offset conv (HMMA fp16 2-pass) =======================
__global__ void __launch_bounds__(512, 1) offconv_mma_kernel(const float* __restrict__ off_b) {
    extern __shared__ __align__(16) char smem[];
    u32 sb = smem_u32(smem);

    int t = threadIdx.x;
    int lane = t & 31;
    int warp = t >> 5;
    int rp = blockIdx.x;
    int b = blockIdx.y;

    int m_base = (warp & 3) * 32;
    int n_base = (warp >> 2) * 8;
    u32 aoff = (u32)((m_base + (lane & 7) + ((lane >> 3) & 1) * 8) * 144 + (lane >> 4) * 16);
    u32 boff = (u32)((n_base + (lane & 7)) * 144 + (lane >> 3) * 16);

    float acc[2][4];
#pragma unroll
    for (int i = 0; i < 2; i++)
#pragma unroll
        for (int r = 0; r < 4; r++) acc[i][r] = 0.f;

    int m = t & 127;
    int kq = t >> 7;
    int hrow = rp * 2 + (m >> 6);
    int wcol = m & 63;
    const float* xpb = g_xp + (size_t)b * C2 * HWP;

    auto gather = [&](int cc, int abuf) {
        int n_ = cc >> 2, kc = cc & 3;
        int hs = hrow + (n_ / 3 - 1);
        int ws = wcol + (n_ % 3 - 1);
        bool inb = ((unsigned)hs < 64u) && ((unsigned)ws < 64u);
        const float* src = xpb + (size_t)(kc * 64 + kq * 16) * HWP + hs * WW + ws;
        u32 hi[8], lo[8];
#pragma unroll
        for (int j2 = 0; j2 < 8; j2++) {
            float v0 = inb ? src[(size_t)(2 * j2) * HWP] : 0.f;
            float v1 = inb ? src[(size_t)(2 * j2 + 1) * HWP] : 0.f;
            split2h(v0, v1, hi[j2], lo[j2]);
        }
        char* ab = smem + OC_A + abuf * 36864 + m * 144 + kq * 32;
        *(uint4*)ab = make_uint4(hi[0], hi[1], hi[2], hi[3]);
        *(uint4*)(ab + 16) = make_uint4(hi[4], hi[5], hi[6], hi[7]);
        *(uint4*)(ab + 18432) = make_uint4(lo[0], lo[1], lo[2], lo[3]);
        *(uint4*)(ab + 18432 + 16) = make_uint4(lo[4], lo[5], lo[6], lo[7]);
    };

    {
        const char* src = (const char*)g_ow;
        for (int u = t; u < 288; u += 512)
            if (u < 288) cpa16(sb + OC_B + u * 16, src + u * 16);
        cpa_commit();
    }
    gather(0, 0);

    for (int cc = 0; cc < 36; cc++) {
        int abuf = cc & 1;
        __syncthreads();

        if (cc + 1 < 36) {
            const char* src = (const char*)g_ow + (size_t)(cc + 1) * 4608;
            u32 dst = sb + OC_B + ((cc + 1) & 1) * 4608;
            for (int u = t; u < 288; u += 512)
                if (u < 288) cpa16(dst + u * 16, src + u * 16);
        }
        cpa_commit();
        if (cc + 1 < 36) gather(cc + 1, abuf ^ 1);
        cpa_wait1();

        u32 sa = sb + OC_A + abuf * 36864;
        u32 sbb = sb + OC_B + abuf * 4608;
#pragma unroll
        for (int kk = 0; kk < 2; kk++) {
            u32 bh[4];
            ldsm4(bh, sbb + boff + kk * 64);
#pragma unroll
            for (int ksh = 0; ksh < 2; ksh++) {
                int ks = kk * 2 + ksh;
                u32 ah[2][4], al[2][4];
#pragma unroll
                for (int mt = 0; mt < 2; mt++) {
                    ldsm4(ah[mt], sa + aoff + mt * 2304 + ks * 32);
                    ldsm4(al[mt], sa + 18432 + aoff + mt * 2304 + ks * 32);
                }
#pragma unroll
                for (int mt = 0; mt < 2; mt++) {
                    mma_f16(acc[mt], ah[mt], bh[2 * ksh], bh[2 * ksh + 1]);
                    mma_f16(acc[mt], al[mt], bh[2 * ksh], bh[2 * ksh + 1]);
                }
            }
        }
    }

    float* ob = g_off + (size_t)b * 18 * HWP;
#pragma unroll
    for (int mt = 0; mt < 2; mt++) {
#pragma unroll
        for (int r = 0; r < 4; r++) {
            int o = n_base + (lane & 3) * 2 + (r & 1);
            int opix = rp * 128 + m_base + mt * 16 + (lane >> 2) + (r >> 1) * 8;
            if (o < 18)
                ob[(size_t)o * HWP + opix] = acc[mt][r] + off_b[o];
        }
    }
}

// ======================= stage 3: deformable sample + HMMA fp16 2-pass + SiLU =======================
// Software-pipelined: gather for chunk cc+1 is split into 4 parts of 4 channels; each
// part's LDGs are issued BEFORE the k-step-p MMA block of chunk cc and consumed
// (bilinear+split+STS) AFTER it, so LDG latency hides under ~500 cyc of tensor work.
// Registers: 64 acc + 16 held floats + frags ~20 + coords ~10 < 128.
__global__ void __launch_bounds__(512, 1) dcn_mma_kernel(float* __restrict__ out) {
    extern __shared__ __align__(16) char smem[];
    u32 sb = smem_u32(smem);

    int t = threadIdx.x;
    int lane = t & 31;
    int warp = t >> 5;
    int rp = blockIdx.x;
    int b = blockIdx.y;

    int m_base = (warp & 3) * 32;
    int n_base = (warp >> 2) * 64;
    u32 aoff = (u32)((m_base + (lane & 7) + ((lane >> 3) & 1) * 8) * 144 + (lane >> 4) * 16);
    u32 boff = (u32)((n_base + (lane & 7) + (lane >> 4) * 8) * 144 + ((lane >> 3) & 1) * 16);

    float acc[2][8][4];
#pragma unroll
    for (int i = 0; i < 2; i++)
#pragma unroll
        for (int j = 0; j < 8; j++)
#pragma unroll
            for (int r = 0; r < 4; r++) acc[i][j][r] = 0.f;

    int m = t & 127;
    int kq = t >> 7;
    int ph = m >> 6;
    int pw_ = m & 63;
    int pix = rp * 128 + m;
    int hrow = rp * 2 + ph;

    const float* xpb = g_xp + (size_t)b * C2 * HWP;
    const float* offb = g_off + (size_t)b * 18 * HWP;

    // full gather (prologue only)
    auto gather = [&](int cc, int abuf) {
        int n_ = cc >> 2, kc = cc & 3;
        float oy = offb[n_ * HWP + pix];
        float ox = offb[(n_ + 9) * HWP + pix];
        float py = (float)hrow + (float)(n_ / 3 - 1) + oy;
        float px = (float)pw_ + (float)(n_ % 3 - 1) + ox;
        py = fminf(fmaxf(py, 0.f), 63.f);
        px = fminf(fmaxf(px, 0.f), 63.f);
        float y0f = floorf(py), x0f = floorf(px);
        int y0 = (int)y0f, x0 = (int)x0f;
        int x1 = min(x0 + 1, 63);
        int y0o = y0 * WW, y1o = min(y0 + 1, 63) * WW;
        float wy = py - y0f, wx = px - x0f;
        float w00 = (1.f - wy) * (1.f - wx);
        float w01 = (1.f - wy) * wx;
        float w10 = wy * (1.f - wx);
        float w11 = wy * wx;

        const float* plane = xpb + (size_t)(kc * 64 + kq * 16) * HWP;
        u32 hi[8], lo[8];
#pragma unroll
        for (int j2 = 0; j2 < 8; j2++) {
            float v[2];
#pragma unroll
            for (int e = 0; e < 2; e++) {
                const float* pl = plane + (size_t)(2 * j2 + e) * HWP;
                v[e] = pl[y0o + x0] * w00 + pl[y0o + x1] * w01
                     + pl[y1o + x0] * w10 + pl[y1o + x1] * w11;
            }
            split2h(v[0], v[1], hi[j2], lo[j2]);
        }
        char* ab = smem + SM_A + abuf * 36864 + m * 144 + kq * 32;
        *(uint4*)ab = make_uint4(hi[0], hi[1], hi[2], hi[3]);
        *(uint4*)(ab + 16) = make_uint4(hi[4], hi[5], hi[6], hi[7]);
        *(uint4*)(ab + 18432) = make_uint4(lo[0], lo[1], lo[2], lo[3]);
        *(uint4*)(ab + 18432 + 16) = make_uint4(lo[4], lo[5], lo[6], lo[7]);
    };

    {
        const char* src = (const char*)g_bt;
        for (int u = t; u < 2304; u += 512)
            cpa16(sb + SM_B + u * 16, src + u * 16);
        cpa_commit();
    }
    gather(0, 0);

    for (int cc = 0; cc < 36; cc++) {
        int abuf = cc & 1;
        __syncthreads();   // A(cc)/B(cc) visible; prior consumers done

        // prefetch B(cc+1)
        if (cc + 1 < 36) {
            const char* srcB = (const char*)g_bt + (size_t)(cc + 1) * 36864;
            u32 dst = sb + SM_B + ((cc + 1) & 1) * 36864;
            for (int u = t; u < 2304; u += 512)
                cpa16(dst + u * 16, srcB + u * 16);
        }
        cpa_commit();
        cpa_wait1();       // B(cc) resident (newest group = B(cc+1) still in flight)

        // coords for chunk cc+1 (uniform branch)
        bool hasNext = (cc + 1 < 36);
        int x0 = 0, x1 = 0, y0o = 0, y1o = 0;
        float w00 = 0.f, w01 = 0.f, w10 = 0.f, w11 = 0.f;
        const float* plane = xpb;
        char* ab = smem;
        if (hasNext) {
            int nc = cc + 1;
            int n_ = nc >> 2, kc = nc & 3;
            float oy = offb[n_ * HWP + pix];
            float ox = offb[(n_ + 9) * HWP + pix];
            float py = (float)hrow + (float)(n_ / 3 - 1) + oy;
            float px = (float)pw_ + (float)(n_ % 3 - 1) + ox;
            py = fminf(fmaxf(py, 0.f), 63.f);
            px = fminf(fmaxf(px, 0.f), 63.f);
            float y0f = floorf(py), x0f = floorf(px);
            int y0 = (int)y0f;
            x0 = (int)x0f;
            x1 = min(x0 + 1, 63);
            y0o = y0 * WW;
            y1o = min(y0 + 1, 63) * WW;
            float wy = py - y0f, wx = px - x0f;
            w00 = (1.f - wy) * (1.f - wx);
            w01 = (1.f - wy) * wx;
            w10 = wy * (1.f - wx);
            w11 = wy * wx;
            plane = xpb + (size_t)(kc * 64 + kq * 16) * HWP;
            ab = smem + SM_A + (abuf ^ 1) * 36864 + m * 144 + kq * 32;
        }

        u32 sa = sb + SM_A + abuf * 36864;
        u32 sbb = sb + SM_B + abuf * 36864;
#pragma unroll
        for (int p = 0; p < 4; p++) {
            // issue part-p gather LDGs (4 channels x 4 corners) — consumed after MMAs
            float r00[4], r01[4], r10[4], r11[4];
            if (hasNext) {
                const float* pl0 = plane + (size_t)(4 * p) * HWP;
#pragma unroll
                for (int e = 0; e < 4; e++) {
                    const float* q = pl0 + (size_t)e * HWP;
                    r00[e] = q[y0o + x0];
                    r01[e] = q[y0o + x1];
                    r10[e] = q[y1o + x0];
                    r11[e] = q[y1o + x1];
                }
            }

            // MMA k-step p on chunk cc
            {
                u32 ah[2][4], al[2][4];
#pragma unroll
                for (int mt = 0; mt < 2; mt++) {
                    ldsm4(ah[mt], sa + aoff + mt * 2304 + p * 32);
                    ldsm4(al[mt], sa + 18432 + aoff + mt * 2304 + p * 32);
                }
#pragma unroll
                for (int ng = 0; ng < 4; ng++) {
                    u32 bh[4];
                    ldsm4(bh, sbb + boff + ng * 2304 + p * 32);
#pragma unroll
                    for (int mt = 0; mt < 2; mt++) {
                        mma_f16(acc[mt][ng * 2 + 0], ah[mt], bh[0], bh[1]);
                        mma_f16(acc[mt][ng * 2 + 1], ah[mt], bh[2], bh[3]);
                        mma_f16(acc[mt][ng * 2 + 0], al[mt], bh[0], bh[1]);
                        mma_f16(acc[mt][ng * 2 + 1], al[mt], bh[2], bh[3]);
                    }
                }
            }

            // consume part-p loads: bilinear + fp16 split + STS into A(cc+1)
            if (hasNext) {
                float v0 = r00[0] * w00 + r01[0] * w01 + r10[0] * w10 + r11[0] * w11;
                float v1 = r00[1] * w00 + r01[1] * w01 + r10[1] * w10 + r11[1] * w11;
                float v2 = r00[2] * w00 + r01[2] * w01 + r10[2] * w10 + r11[2] * w11;
                float v3 = r00[3] * w00 + r01[3] * w01 + r10[3] * w10 + r11[3] * w11;
                u32 h0, l0, h1, l1;
                split2h(v0, v1, h0, l0);
                split2h(v2, v3, h1, l1);
                *(uint2*)(ab + p * 8) = make_uint2(h0, h1);
                *(uint2*)(ab + 18432 + p * 8) = make_uint2(l0, l1);
            }
        }
    }

    float* ob = out + (size_t)b * C2 * HWP;
#pragma unroll
    for (int mt = 0; mt < 2; mt++) {
#pragma unroll
        for (int j = 0; j < 8; j++) {
#pragma unroll
            for (int r = 0; r < 4; r++) {
                int o = n_base + j * 8 + (lane & 3) * 2 + (r & 1);
                int opix = rp * 128 + m_base + mt * 16 + (lane >> 2) + (r >> 1) * 8;
                float f = acc[mt][j][r];
                f = f / (1.f + __expf(-f));
                ob[(size_t)o * HWP + opix] = f;
            }
        }
    }
}

// ======================= launch =======================
extern "C" void kernel_launch(void* const* d_in, const int* in_sizes, int n_in,
                              void* d_out, int out_size) {
    const float* x = (const float*)d_in[0];
    const float* pw_w = (const float*)d_in[1];
    const float* gamma = (const float*)d_in[2];
    const float* beta = (const float*)d_in[3];
    const float* mean = (const float*)d_in[4];
    const float* var = (const float*)d_in[5];
    const float* off_w = (const float*)d_in[6];
    const float* off_b = (const float*)d_in[7];
    const float* dcn_w = (const float*)d_in[8];
    float* out = (float*)d_out;

    (void)in_sizes; (void)n_in; (void)out_size;

    cudaFuncSetAttribute(pw_mma_kernel, cudaFuncAttributeMaxDynamicSharedMemorySize, PW_DYN);
    cudaFuncSetAttribute(offconv_mma_kernel, cudaFuncAttributeMaxDynamicSharedMemorySize, OC_DYN);
    cudaFuncSetAttribute(dcn_mma_kernel, cudaFuncAttributeMaxDynamicSharedMemorySize, SM_DYN);

    prep_all<<<38, 256>>>(gamma, beta, mean, var, pw_w, dcn_w, off_w);
    pw_mma_kernel<<<dim3(32, BB), 512, PW_DYN>>>(x);
    offconv_mma_kernel<<<dim3(32, BB), 512, OC_DYN>>>(off_b);
    dcn_mma_kernel<<<dim3(32, BB), 512, SM_DYN>>>(out);
}

// round 14
// speedup vs baseline: 6.2069x; 1.0016x over previous
#include <cuda_runtime.h>
#include <cuda_bf16.h>
#include <cuda_fp16.h>
#include <math.h>

#define HH 64
#define WW 64
#define HWP 4096
#define BB 4
#define C1 128
#define C2 256
#define NK 9

typedef unsigned int u32;
typedef unsigned long long u64;

// -------- device scratch --------
__device__ float g_xp[BB * C2 * HWP];          // pointwise+BN output (16.8 MB)
__device__ float g_off[BB * 2 * NK * HWP];     // offset conv output
__device__ float g_scale[C2];
__device__ float g_bias[C2];
// dcn B tiles (fp16, hi only): 36 chunks x [256 o rows][72 cols]
__device__ __align__(128) __half g_bt[36 * 256 * 72];
// pw B tiles (bf16 split): 2 chunks x [hi|lo] x [256 o rows][72 cols]
__device__ __align__(128) __nv_bfloat16 g_pwt2[2 * 2 * 256 * 72];
// offconv B tiles (fp16, hi only): 36 chunks x [32 rows][72 cols]
__device__ __align__(128) __half g_ow[36 * 32 * 72];

// ======== SMEM layouts (bytes) ========
// dcn: B 2 x 36864 | A 2 x (18432 hi + 18432 lo)
#define SM_B   0
#define SM_A   73728
#define SM_DYN 147456
// pw: B 2 chunks x 73728 | A 2 bufs x 36864
#define PW_B   0
#define PW_A   147456
#define PW_DYN 221184
// offconv: B 2 bufs x 4608 | A 2 bufs x 36864
#define OC_B   0
#define OC_A   9216
#define OC_DYN 82944

// -------- PTX helpers (baseline PTX only; tcgen05 is sm_103a-gated and unusable) --------
__device__ __forceinline__ u32 smem_u32(const void* p) {
    u32 a;
    asm("{ .reg .u64 t; cvta.to.shared.u64 t, %1; cvt.u32.u64 %0, t; }" : "=r"(a) : "l"(p));
    return a;
}
__device__ __forceinline__ void cpa16(u32 dst, const void* src) {
    asm volatile("cp.async.cg.shared.global [%0], [%1], 16;" :: "r"(dst), "l"(src));
}
__device__ __forceinline__ void cpa_commit() {
    asm volatile("cp.async.commit_group;" ::: "memory");
}
__device__ __forceinline__ void cpa_wait0() {
    asm volatile("cp.async.wait_group 0;" ::: "memory");
}
__device__ __forceinline__ void cpa_wait1() {
    asm volatile("cp.async.wait_group 1;" ::: "memory");
}
__device__ __forceinline__ void ldsm4(u32* r, u32 addr) {
    asm volatile("ldmatrix.sync.aligned.m8n8.x4.shared.b16 {%0,%1,%2,%3}, [%4];"
                 : "=r"(r[0]), "=r"(r[1]), "=r"(r[2]), "=r"(r[3]) : "r"(addr));
}
__device__ __forceinline__ void mma_bf16(float* d, const u32* a, u32 b0, u32 b1) {
    asm volatile(
        "mma.sync.aligned.m16n8k16.row.col.f32.bf16.bf16.f32 "
        "{%0,%1,%2,%3}, {%4,%5,%6,%7}, {%8,%9}, {%0,%1,%2,%3};"
        : "+f"(d[0]), "+f"(d[1]), "+f"(d[2]), "+f"(d[3])
        : "r"(a[0]), "r"(a[1]), "r"(a[2]), "r"(a[3]), "r"(b0), "r"(b1));
}
__device__ __forceinline__ void mma_f16(float* d, const u32* a, u32 b0, u32 b1) {
    asm volatile(
        "mma.sync.aligned.m16n8k16.row.col.f32.f16.f16.f32 "
        "{%0,%1,%2,%3}, {%4,%5,%6,%7}, {%8,%9}, {%0,%1,%2,%3};"
        : "+f"(d[0]), "+f"(d[1]), "+f"(d[2]), "+f"(d[3])
        : "r"(a[0]), "r"(a[1]), "r"(a[2]), "r"(a[3]), "r"(b0), "r"(b1));
}
__device__ __forceinline__ u32 cvt_bf16x2(float hi_val, float lo_val) {
    u32 r;
    asm("cvt.rn.bf16x2.f32 %0, %1, %2;" : "=r"(r) : "f"(hi_val), "f"(lo_val));
    return r;
}
// bf16 split (pw path)
__device__ __forceinline__ void split2(float v0, float v1, u32& hi, u32& lo) {
    u32 hp = cvt_bf16x2(v1, v0);
    hi = hp;
    float h0 = __uint_as_float(hp << 16);
    float h1 = __uint_as_float(hp & 0xffff0000u);
    lo = cvt_bf16x2(v1 - h1, v0 - h0);
}
// fp16 split (dcn/offconv path): a = ah + al exactly to ~2^-22
__device__ __forceinline__ void split2h(float v0, float v1, u32& hi, u32& lo) {
    __half2 h = __floats2half2_rn(v0, v1);
    hi = *(u32*)&h;
    float2 hf = __half22float2(h);
    __half2 l = __floats2half2_rn(v0 - hf.x, v1 - hf.y);
    lo = *(u32*)&l;
}

// ======================= fused prep kernel (single launch) =======================
__global__ void prep_all(const float* __restrict__ gamma, const float* __restrict__ beta,
                         const float* __restrict__ mean, const float* __restrict__ var,
                         const float* __restrict__ pw, const float* __restrict__ dcn,
                         const float* __restrict__ off_w) {
    int bid = blockIdx.x;
    int t = threadIdx.x;   // 0..255
    if (bid < 2) {
        if (bid == 0) {
            float s = gamma[t] * rsqrtf(var[t] + 1e-5f);
            g_scale[t] = s;
            g_bias[t] = beta[t] - mean[t] * s;
        }
        int kc = bid;
        __nv_bfloat16* hi = g_pwt2 + ((size_t)(kc * 2 + 0) * 256 + t) * 72;
        __nv_bfloat16* lo = g_pwt2 + ((size_t)(kc * 2 + 1) * 256 + t) * 72;
#pragma unroll 4
        for (int cl = 0; cl < 64; cl++) {
            float w = pw[t * C1 + kc * 64 + cl];
            __nv_bfloat16 h = __float2bfloat16(w);
            hi[cl] = h;
            lo[cl] = __float2bfloat16(w - __bfloat162float(h));
        }
        for (int cl = 64; cl < 72; cl++) { hi[cl] = __float2bfloat16(0.f); lo[cl] = __float2bfloat16(0.f); }
    } else {
        int chunk = bid - 2;            // 0..35
        int n_ = chunk >> 2, kc = chunk & 3;
        __half* bt = g_bt + ((size_t)chunk * 256 + t) * 72;
#pragma unroll 4
        for (int cl = 0; cl < 64; cl++)
            bt[cl] = __float2half_rn(dcn[(t * C2 + kc * 64 + cl) * NK + n_]);
        for (int cl = 64; cl < 72; cl++) bt[cl] = __float2half_rn(0.f);
        {
            int o = t & 31;
            int grp = t >> 5;
            __half* ow = g_ow + ((size_t)chunk * 32 + o) * 72;
#pragma unroll
            for (int i = 0; i < 8; i++) {
                int cl = grp * 8 + i;
                float w = (o < 18) ? off_w[(o * C2 + kc * 64 + cl) * 9 + n_] : 0.f;
                ow[cl] = __float2half_rn(w);
            }
            if (grp == 0)
                for (int cl = 64; cl < 72; cl++) ow[cl] = __float2half_rn(0.f);
        }
    }
}

// ======================= stage 1: pointwise conv + BN (HMMA bf16 3-pass) =======================
__global__ void __launch_bounds__(512, 1) pw_mma_kernel(const float* __restrict__ x) {
    extern __shared__ __align__(16) char smem[];
    u32 sb = smem_u32(smem);

    int t = threadIdx.x;
    int lane = t & 31;
    int warp = t >> 5;
    int rp = blockIdx.x;
    int b = blockIdx.y;

    int m_base = (warp & 3) * 32;
    int n_base = (warp >> 2) * 64;
    u32 aoff = (u32)((m_base + (lane & 7) + ((lane >> 3) & 1) * 8) * 144 + (lane >> 4) * 16);
    u32 boff = (u32)((n_base + (lane & 7) + (lane >> 4) * 8) * 144 + ((lane >> 3) & 1) * 16);

    float acc[2][8][4];
#pragma unroll
    for (int i = 0; i < 2; i++)
#pragma unroll
        for (int j = 0; j < 8; j++)
#pragma unroll
            for (int r = 0; r < 4; r++) acc[i][j][r] = 0.f;

    int m = t & 127;
    int kq = t >> 7;
    int pix = rp * 128 + m;

    {
        const char* src = (const char*)g_pwt2;
        for (int u = t; u < 9216; u += 512)
            cpa16(sb + PW_B + u * 16, src + u * 16);
        cpa_commit();
    }

    const float* xb = x + (size_t)b * C1 * HWP + pix;
#pragma unroll
    for (int kc = 0; kc < 2; kc++) {
        u32 hi[8], lo[8];
#pragma unroll
        for (int j2 = 0; j2 < 8; j2++) {
            float v0 = xb[(size_t)(kc * 64 + kq * 16 + 2 * j2) * HWP];
            float v1 = xb[(size_t)(kc * 64 + kq * 16 + 2 * j2 + 1) * HWP];
            split2(v0, v1, hi[j2], lo[j2]);
        }
        char* ab = smem + PW_A + kc * 36864 + m * 144 + kq * 32;
        *(uint4*)ab = make_uint4(hi[0], hi[1], hi[2], hi[3]);
        *(uint4*)(ab + 16) = make_uint4(hi[4], hi[5], hi[6], hi[7]);
        *(uint4*)(ab + 18432) = make_uint4(lo[0], lo[1], lo[2], lo[3]);
        *(uint4*)(ab + 18432 + 16) = make_uint4(lo[4], lo[5], lo[6], lo[7]);
    }
    cpa_wait0();
    __syncthreads();

#pragma unroll
    for (int kc = 0; kc < 2; kc++) {
        u32 sa = sb + PW_A + kc * 36864;
        u32 sbb = sb + PW_B + kc * 73728;
#pragma unroll
        for (int ks = 0; ks < 4; ks++) {
            u32 ah[2][4], al[2][4];
#pragma unroll
            for (int mt = 0; mt < 2; mt++) {
                ldsm4(ah[mt], sa + aoff + mt * 2304 + ks * 32);
                ldsm4(al[mt], sa + 18432 + aoff + mt * 2304 + ks * 32);
            }
#pragma unroll
            for (int ng = 0; ng < 4; ng++) {
                u32 bh[4], bl[4];
                ldsm4(bh, sbb + boff + ng * 2304 + ks * 32);
                ldsm4(bl, sbb + 36864 + boff + ng * 2304 + ks * 32);
#pragma unroll
                for (int mt = 0; mt < 2; mt++) {
                    mma_bf16(acc[mt][ng * 2 + 0], ah[mt], bh[0], bh[1]);
                    mma_bf16(acc[mt][ng * 2 + 1], ah[mt], bh[2], bh[3]);
                    mma_bf16(acc[mt][ng * 2 + 0], ah[mt], bl[0], bl[1]);
                    mma_bf16(acc[mt][ng * 2 + 1], ah[mt], bl[2], bl[3]);
                    mma_bf16(acc[mt][ng * 2 + 0], al[mt], bh[0], bh[1]);
                    mma_bf16(acc[mt][ng * 2 + 1], al[mt], bh[2], bh[3]);
                }
            }
        }
    }

    float* ob = g_xp + (size_t)b * C2 * HWP;
#pragma unroll
    for (int mt = 0; mt < 2; mt++) {
#pragma unroll
        for (int j = 0; j < 8; j++) {
#pragma unroll
            for (int r = 0; r < 4; r++) {
                int o = n_base + j * 8 + (lane & 3) * 2 + (r & 1);
                int opix = rp * 128 + m_base + mt * 16 + (lane >> 2) + (r >> 1) * 8;
                ob[(size_t)o * HWP + opix] = acc[mt][j][r] * g_scale[o] + g_bias[o];
            }
        }
    }
}

// ======================= stage 2: 3x3 offset conv (HMMA fp16 2-pass) =======================
__global__ void __launch_bounds__(512, 1) offconv_mma_kernel(const float* __restrict__ off_b) {
    extern __shared__ __align__(16) char smem[];
    u32 sb = smem_u32(smem);

    int t = threadIdx.x;
    int lane = t & 31;
    int warp = t >> 5;
    int rp = blockIdx.x;
    int b = blockIdx.y;

    int m_base = (warp & 3) * 32;
    int n_base = (warp >> 2) * 8;
    u32 aoff = (u32)((m_base + (lane & 7) + ((lane >> 3) & 1) * 8) * 144 + (lane >> 4) * 16);
    u32 boff = (u32)((n_base + (lane & 7)) * 144 + (lane >> 3) * 16);

    float acc[2][4];
#pragma unroll
    for (int i = 0; i < 2; i++)
#pragma unroll
        for (int r = 0; r < 4; r++) acc[i][r] = 0.f;

    int m = t & 127;
    int kq = t >> 7;
    int hrow = rp * 2 + (m >> 6);
    int wcol = m & 63;
    const float* xpb = g_xp + (size_t)b * C2 * HWP;

    auto gather = [&](int cc, int abuf) {
        int n_ = cc >> 2, kc = cc & 3;
        int hs = hrow + (n_ / 3 - 1);
        int ws = wcol + (n_ % 3 - 1);
        bool inb = ((unsigned)hs < 64u) && ((unsigned)ws < 64u);
        const float* src = xpb + (size_t)(kc * 64 + kq * 16) * HWP + hs * WW + ws;
        u32 hi[8], lo[8];
#pragma unroll
        for (int j2 = 0; j2 < 8; j2++) {
            float v0 = inb ? src[(size_t)(2 * j2) * HWP] : 0.f;
            float v1 = inb ? src[(size_t)(2 * j2 + 1) * HWP] : 0.f;
            split2h(v0, v1, hi[j2], lo[j2]);
        }
        char* ab = smem + OC_A + abuf * 36864 + m * 144 + kq * 32;
        *(uint4*)ab = make_uint4(hi[0], hi[1], hi[2], hi[3]);
        *(uint4*)(ab + 16) = make_uint4(hi[4], hi[5], hi[6], hi[7]);
        *(uint4*)(ab + 18432) = make_uint4(lo[0], lo[1], lo[2], lo[3]);
        *(uint4*)(ab + 18432 + 16) = make_uint4(lo[4], lo[5], lo[6], lo[7]);
    };

    {
        const char* src = (const char*)g_ow;
        for (int u = t; u < 288; u += 512)
            if (u < 288) cpa16(sb + OC_B + u * 16, src + u * 16);
        cpa_commit();
    }
    gather(0, 0);

    for (int cc = 0; cc < 36; cc++) {
        int abuf = cc & 1;
        __syncthreads();

        if (cc + 1 < 36) {
            const char* src = (const char*)g_ow + (size_t)(cc + 1) * 4608;
            u32 dst = sb + OC_B + ((cc + 1) & 1) * 4608;
            for (int u = t; u < 288; u += 512)
                if (u < 288) cpa16(dst + u * 16, src + u * 16);
        }
        cpa_commit();
        if (cc + 1 < 36) gather(cc + 1, abuf ^ 1);
        cpa_wait1();

        u32 sa = sb + OC_A + abuf * 36864;
        u32 sbb = sb + OC_B + abuf * 4608;
#pragma unroll
        for (int kk = 0; kk < 2; kk++) {
            u32 bh[4];
            ldsm4(bh, sbb + boff + kk * 64);
#pragma unroll
            for (int ksh = 0; ksh < 2; ksh++) {
                int ks = kk * 2 + ksh;
                u32 ah[2][4], al[2][4];
#pragma unroll
                for (int mt = 0; mt < 2; mt++) {
                    ldsm4(ah[mt], sa + aoff + mt * 2304 + ks * 32);
                    ldsm4(al[mt], sa + 18432 + aoff + mt * 2304 + ks * 32);
                }
#pragma unroll
                for (int mt = 0; mt < 2; mt++) {
                    mma_f16(acc[mt], ah[mt], bh[2 * ksh], bh[2 * ksh + 1]);
                    mma_f16(acc[mt], al[mt], bh[2 * ksh], bh[2 * ksh + 1]);
                }
            }
        }
    }

    float* ob = g_off + (size_t)b * 18 * HWP;
#pragma unroll
    for (int mt = 0; mt < 2; mt++) {
#pragma unroll
        for (int r = 0; r < 4; r++) {
            int o = n_base + (lane & 3) * 2 + (r & 1);
            int opix = rp * 128 + m_base + mt * 16 + (lane >> 2) + (r >> 1) * 8;
            if (o < 18)
                ob[(size_t)o * HWP + opix] = acc[mt][r] + off_b[o];
        }
    }
}

// ======================= stage 3: warp-specialized dcn (producer/consumer) =======================
// 640 threads: warps 0..15 = consumers (pure ldsm+mma, tiling unchanged), warps 16..19 =
// producers (1/SMSP; 128 threads = 1 thread/pixel, each produces all 64 chans/chunk +
// issues B cp.async). One __syncthreads per chunk swaps double buffers. Producers own
// cp.async groups end-to-end (issue, commit, wait) — completion + barrier = CTA visibility.
__global__ void __launch_bounds__(640, 1) dcn_mma_kernel(float* __restrict__ out) {
    extern __shared__ __align__(16) char smem[];
    u32 sb = smem_u32(smem);

    int t = threadIdx.x;
    int rp = blockIdx.x;
    int b = blockIdx.y;

    const float* xpb = g_xp + (size_t)b * C2 * HWP;

    if (t >= 512) {
        // ---------------- producer warps ----------------
        int g = t - 512;                // pixel 0..127
        int pix = rp * 128 + g;
        int hrow = rp * 2 + (g >> 6);
        int pcol = g & 63;
        const float* offb = g_off + (size_t)b * 18 * HWP;

        // produce A(cc) for all 64 channels of pixel g
        auto produce = [&](int cc) {
            int n_ = cc >> 2, kc = cc & 3;
            float oy = offb[n_ * HWP + pix];
            float ox = offb[(n_ + 9) * HWP + pix];
            float py = (float)hrow + (float)(n_ / 3 - 1) + oy;
            float px = (float)pcol + (float)(n_ % 3 - 1) + ox;
            py = fminf(fmaxf(py, 0.f), 63.f);
            px = fminf(fmaxf(px, 0.f), 63.f);
            float y0f = floorf(py), x0f = floorf(px);
            int y0 = (int)y0f, x0 = (int)x0f;
            int x1 = min(x0 + 1, 63);
            int y0o = y0 * WW, y1o = min(y0 + 1, 63) * WW;
            float wy = py - y0f, wx = px - x0f;
            float w00 = (1.f - wy) * (1.f - wx);
            float w01 = (1.f - wy) * wx;
            float w10 = wy * (1.f - wx);
            float w11 = wy * wx;

            const float* plane = xpb + (size_t)(kc * 64) * HWP;
            char* ab = smem + SM_A + (cc & 1) * 36864 + g * 144;
#pragma unroll 4
            for (int c4 = 0; c4 < 16; c4++) {
                float v[4];
#pragma unroll
                for (int e = 0; e < 4; e++) {
                    const float* q = plane + (size_t)(c4 * 4 + e) * HWP;
                    v[e] = q[y0o + x0] * w00 + q[y0o + x1] * w01
                         + q[y1o + x0] * w10 + q[y1o + x1] * w11;
                }
                u32 h0, l0, h1, l1;
                split2h(v[0], v[1], h0, l0);
                split2h(v[2], v[3], h1, l1);
                *(uint2*)(ab + c4 * 8) = make_uint2(h0, h1);
                *(uint2*)(ab + 18432 + c4 * 8) = make_uint2(l0, l1);
            }
        };

        // prologue: B(0) + A(0)
        {
            const char* src = (const char*)g_bt;
            for (int u = g; u < 2304; u += 128)
                cpa16(sb + SM_B + u * 16, src + u * 16);
            cpa_commit();
        }
        produce(0);
        cpa_wait0();
        __syncthreads();   // publish A(0)/B(0)

        for (int cc = 0; cc < 36; cc++) {
            if (cc + 1 < 36) {
                const char* srcB = (const char*)g_bt + (size_t)(cc + 1) * 36864;
                u32 dst = sb + SM_B + ((cc + 1) & 1) * 36864;
                for (int u = g; u < 2304; u += 128)
                    cpa16(dst + u * 16, srcB + u * 16);
                cpa_commit();
                produce(cc + 1);
                cpa_wait0();
            }
            __syncthreads();   // publish A(cc+1)/B(cc+1); consumers done with buf cc
        }
        return;
    }

    // ---------------- consumer warps ----------------
    int lane = t & 31;
    int warp = t >> 5;
    int m_base = (warp & 3) * 32;
    int n_base = (warp >> 2) * 64;
    u32 aoff = (u32)((m_base + (lane & 7) + ((lane >> 3) & 1) * 8) * 144 + (lane >> 4) * 16);
    u32 boff = (u32)((n_base + (lane & 7) + (lane >> 4) * 8) * 144 + ((lane >> 3) & 1) * 16);

    float acc[2][8][4];
#pragma unroll
    for (int i = 0; i < 2; i++)
#pragma unroll
        for (int j = 0; j < 8; j++)
#pragma unroll
            for (int r = 0; r < 4; r++) acc[i][j][r] = 0.f;

    __syncthreads();   // wait A(0)/B(0)

    for (int cc = 0; cc < 36; cc++) {
        u32 sa = sb + SM_A + (cc & 1) * 36864;
        u32 sbb = sb + SM_B + (cc & 1) * 36864;
#pragma unroll
        for (int p = 0; p < 4; p++) {
            u32 ah[2][4], al[2][4];
#pragma unroll
            for (int mt = 0; mt < 2; mt++) {
                ldsm4(ah[mt], sa + aoff + mt * 2304 + p * 32);
                ldsm4(al[mt], sa + 18432 + aoff + mt * 2304 + p * 32);
            }
#pragma unroll
            for (int ng = 0; ng < 4; ng++) {
                u32 bh[4];
                ldsm4(bh, sbb + boff + ng * 2304 + p * 32);
#pragma unroll
                for (int mt = 0; mt < 2; mt++) {
                    mma_f16(acc[mt][ng * 2 + 0], ah[mt], bh[0], bh[1]);
                    mma_f16(acc[mt][ng * 2 + 1], ah[mt], bh[2], bh[3]);
                    mma_f16(acc[mt][ng * 2 + 0], al[mt], bh[0], bh[1]);
                    mma_f16(acc[mt][ng * 2 + 1], al[mt], bh[2], bh[3]);
                }
            }
        }
        __syncthreads();   // done with buf cc; producers publish cc+1
    }

    // epilogue: SiLU + store
    float* ob = out + (size_t)b * C2 * HWP;
#pragma unroll
    for (int mt = 0; mt < 2; mt++) {
#pragma unroll
        for (int j = 0; j < 8; j++) {
#pragma unroll
            for (int r = 0; r < 4; r++) {
                int o = n_base + j * 8 + (lane & 3) * 2 + (r & 1);
                int opix = rp * 128 + m_base + mt * 16 + (lane >> 2) + (r >> 1) * 8;
                float f = acc[mt][j][r];
                f = f / (1.f + __expf(-f));
                ob[(size_t)o * HWP + opix] = f;
            }
        }
    }
}

// ======================= launch =======================
extern "C" void kernel_launch(void* const* d_in, const int* in_sizes, int n_in,
                              void* d_out, int out_size) {
    const float* x = (const float*)d_in[0];
    const float* pw_w = (const float*)d_in[1];
    const float* gamma = (const float*)d_in[2];
    const float* beta = (const float*)d_in[3];
    const float* mean = (const float*)d_in[4];
    const float* var = (const float*)d_in[5];
    const float* off_w = (const float*)d_in[6];
    const float* off_b = (const float*)d_in[7];
    const float* dcn_w = (const float*)d_in[8];
    float* out = (float*)d_out;

    (void)in_sizes; (void)n_in; (void)out_size;

    cudaFuncSetAttribute(pw_mma_kernel, cudaFuncAttributeMaxDynamicSharedMemorySize, PW_DYN);
    cudaFuncSetAttribute(offconv_mma_kernel, cudaFuncAttributeMaxDynamicSharedMemorySize, OC_DYN);
    cudaFuncSetAttribute(dcn_mma_kernel, cudaFuncAttributeMaxDynamicSharedMemorySize, SM_DYN);

    prep_all<<<38, 256>>>(gamma, beta, mean, var, pw_w, dcn_w, off_w);
    pw_mma_kernel<<<dim3(32, BB), 512, PW_DYN>>>(x);
    offconv_mma_kernel<<<dim3(32, BB), 512, OC_DYN>>>(off_b);
    dcn_mma_kernel<<<dim3(32, BB), 640, SM_DYN>>>(out);
}

// round 15
// speedup vs baseline: 6.7496x; 1.0874x over previous
#include <cuda_runtime.h>
#include <cuda_bf16.h>
#include <cuda_fp16.h>
#include <math.h>

#define HH 64
#define WW 64
#define HWP 4096
#define BB 4
#define C1 128
#define C2 256
#define NK 9

typedef unsigned int u32;
typedef unsigned long long u64;

// -------- device scratch --------
__device__ float g_xp[BB * C2 * HWP];          // pointwise+BN output (16.8 MB)
__device__ float g_off[BB * 2 * NK * HWP];     // offset conv output
__device__ float g_scale[C2];
__device__ float g_bias[C2];
// dcn B tiles (fp16, hi only): 36 chunks x [256 o rows][72 cols]
__device__ __align__(128) __half g_bt[36 * 256 * 72];
// pw B tiles (bf16 split): 2 chunks x [hi|lo] x [256 o rows][72 cols]
__device__ __align__(128) __nv_bfloat16 g_pwt2[2 * 2 * 256 * 72];
// offconv B tiles (fp16, hi only): 36 chunks x [32 rows][72 cols]
__device__ __align__(128) __half g_ow[36 * 32 * 72];

// ======== SMEM layouts (bytes) ========
// dcn: B 2 x 36864 | A 2 x (18432 hi + 18432 lo)
#define SM_B   0
#define SM_A   73728
#define SM_DYN 147456
// pw: B 2 chunks x 73728 | A 2 bufs x 36864
#define PW_B   0
#define PW_A   147456
#define PW_DYN 221184
// offconv: B 2 bufs x 4608 | A 2 bufs x 36864
#define OC_B   0
#define OC_A   9216
#define OC_DYN 82944

// -------- PTX helpers (baseline PTX only; tcgen05 is sm_103a-gated and unusable) --------
__device__ __forceinline__ u32 smem_u32(const void* p) {
    u32 a;
    asm("{ .reg .u64 t; cvta.to.shared.u64 t, %1; cvt.u32.u64 %0, t; }" : "=r"(a) : "l"(p));
    return a;
}
__device__ __forceinline__ void cpa16(u32 dst, const void* src) {
    asm volatile("cp.async.cg.shared.global [%0], [%1], 16;" :: "r"(dst), "l"(src));
}
__device__ __forceinline__ void cpa_commit() {
    asm volatile("cp.async.commit_group;" ::: "memory");
}
__device__ __forceinline__ void cpa_wait0() {
    asm volatile("cp.async.wait_group 0;" ::: "memory");
}
__device__ __forceinline__ void cpa_wait1() {
    asm volatile("cp.async.wait_group 1;" ::: "memory");
}
__device__ __forceinline__ void ldsm4(u32* r, u32 addr) {
    asm volatile("ldmatrix.sync.aligned.m8n8.x4.shared.b16 {%0,%1,%2,%3}, [%4];"
                 : "=r"(r[0]), "=r"(r[1]), "=r"(r[2]), "=r"(r[3]) : "r"(addr));
}
__device__ __forceinline__ void mma_bf16(float* d, const u32* a, u32 b0, u32 b1) {
    asm volatile(
        "mma.sync.aligned.m16n8k16.row.col.f32.bf16.bf16.f32 "
        "{%0,%1,%2,%3}, {%4,%5,%6,%7}, {%8,%9}, {%0,%1,%2,%3};"
        : "+f"(d[0]), "+f"(d[1]), "+f"(d[2]), "+f"(d[3])
        : "r"(a[0]), "r"(a[1]), "r"(a[2]), "r"(a[3]), "r"(b0), "r"(b1));
}
__device__ __forceinline__ void mma_f16(float* d, const u32* a, u32 b0, u32 b1) {
    asm volatile(
        "mma.sync.aligned.m16n8k16.row.col.f32.f16.f16.f32 "
        "{%0,%1,%2,%3}, {%4,%5,%6,%7}, {%8,%9}, {%0,%1,%2,%3};"
        : "+f"(d[0]), "+f"(d[1]), "+f"(d[2]), "+f"(d[3])
        : "r"(a[0]), "r"(a[1]), "r"(a[2]), "r"(a[3]), "r"(b0), "r"(b1));
}
__device__ __forceinline__ u32 cvt_bf16x2(float hi_val, float lo_val) {
    u32 r;
    asm("cvt.rn.bf16x2.f32 %0, %1, %2;" : "=r"(r) : "f"(hi_val), "f"(lo_val));
    return r;
}
// bf16 split (pw path)
__device__ __forceinline__ void split2(float v0, float v1, u32& hi, u32& lo) {
    u32 hp = cvt_bf16x2(v1, v0);
    hi = hp;
    float h0 = __uint_as_float(hp << 16);
    float h1 = __uint_as_float(hp & 0xffff0000u);
    lo = cvt_bf16x2(v1 - h1, v0 - h0);
}
// fp16 split (dcn/offconv path): a = ah + al exactly to ~2^-22
__device__ __forceinline__ void split2h(float v0, float v1, u32& hi, u32& lo) {
    __half2 h = __floats2half2_rn(v0, v1);
    hi = *(u32*)&h;
    float2 hf = __half22float2(h);
    __half2 l = __floats2half2_rn(v0 - hf.x, v1 - hf.y);
    lo = *(u32*)&l;
}

// ======================= fused prep kernel (single launch) =======================
__global__ void prep_all(const float* __restrict__ gamma, const float* __restrict__ beta,
                         const float* __restrict__ mean, const float* __restrict__ var,
                         const float* __restrict__ pw, const float* __restrict__ dcn,
                         const float* __restrict__ off_w) {
    int bid = blockIdx.x;
    int t = threadIdx.x;   // 0..255
    if (bid < 2) {
        if (bid == 0) {
            float s = gamma[t] * rsqrtf(var[t] + 1e-5f);
            g_scale[t] = s;
            g_bias[t] = beta[t] - mean[t] * s;
        }
        int kc = bid;
        __nv_bfloat16* hi = g_pwt2 + ((size_t)(kc * 2 + 0) * 256 + t) * 72;
        __nv_bfloat16* lo = g_pwt2 + ((size_t)(kc * 2 + 1) * 256 + t) * 72;
#pragma unroll 4
        for (int cl = 0; cl < 64; cl++) {
            float w = pw[t * C1 + kc * 64 + cl];
            __nv_bfloat16 h = __float2bfloat16(w);
            hi[cl] = h;
            lo[cl] = __float2bfloat16(w - __bfloat162float(h));
        }
        for (int cl = 64; cl < 72; cl++) { hi[cl] = __float2bfloat16(0.f); lo[cl] = __float2bfloat16(0.f); }
    } else {
        int chunk = bid - 2;            // 0..35
        int n_ = chunk >> 2, kc = chunk & 3;
        __half* bt = g_bt + ((size_t)chunk * 256 + t) * 72;
#pragma unroll 4
        for (int cl = 0; cl < 64; cl++)
            bt[cl] = __float2half_rn(dcn[(t * C2 + kc * 64 + cl) * NK + n_]);
        for (int cl = 64; cl < 72; cl++) bt[cl] = __float2half_rn(0.f);
        {
            int o = t & 31;
            int grp = t >> 5;
            __half* ow = g_ow + ((size_t)chunk * 32 + o) * 72;
#pragma unroll
            for (int i = 0; i < 8; i++) {
                int cl = grp * 8 + i;
                float w = (o < 18) ? off_w[(o * C2 + kc * 64 + cl) * 9 + n_] : 0.f;
                ow[cl] = __float2half_rn(w);
            }
            if (grp == 0)
                for (int cl = 64; cl < 72; cl++) ow[cl] = __float2half_rn(0.f);
        }
    }
}

// ======================= stage 1: pointwise conv + BN (HMMA bf16 3-pass) =======================
__global__ void __launch_bounds__(512, 1) pw_mma_kernel(const float* __restrict__ x) {
    extern __shared__ __align__(16) char smem[];
    u32 sb = smem_u32(smem);

    int t = threadIdx.x;
    int lane = t & 31;
    int warp = t >> 5;
    int rp = blockIdx.x;
    int b = blockIdx.y;

    int m_base = (warp & 3) * 32;
    int n_base = (warp >> 2) * 64;
    u32 aoff = (u32)((m_base + (lane & 7) + ((lane >> 3) & 1) * 8) * 144 + (lane >> 4) * 16);
    u32 boff = (u32)((n_base + (lane & 7) + (lane >> 4) * 8) * 144 + ((lane >> 3) & 1) * 16);

    float acc[2][8][4];
#pragma unroll
    for (int i = 0; i < 2; i++)
#pragma unroll
        for (int j = 0; j < 8; j++)
#pragma unroll
            for (int r = 0; r < 4; r++) acc[i][j][r] = 0.f;

    int m = t & 127;
    int kq = t >> 7;
    int pix = rp * 128 + m;

    {
        const char* src = (const char*)g_pwt2;
        for (int u = t; u < 9216; u += 512)
            cpa16(sb + PW_B + u * 16, src + u * 16);
        cpa_commit();
    }

    const float* xb = x + (size_t)b * C1 * HWP + pix;
#pragma unroll
    for (int kc = 0; kc < 2; kc++) {
        u32 hi[8], lo[8];
#pragma unroll
        for (int j2 = 0; j2 < 8; j2++) {
            float v0 = xb[(size_t)(kc * 64 + kq * 16 + 2 * j2) * HWP];
            float v1 = xb[(size_t)(kc * 64 + kq * 16 + 2 * j2 + 1) * HWP];
            split2(v0, v1, hi[j2], lo[j2]);
        }
        char* ab = smem + PW_A + kc * 36864 + m * 144 + kq * 32;
        *(uint4*)ab = make_uint4(hi[0], hi[1], hi[2], hi[3]);
        *(uint4*)(ab + 16) = make_uint4(hi[4], hi[5], hi[6], hi[7]);
        *(uint4*)(ab + 18432) = make_uint4(lo[0], lo[1], lo[2], lo[3]);
        *(uint4*)(ab + 18432 + 16) = make_uint4(lo[4], lo[5], lo[6], lo[7]);
    }
    cpa_wait0();
    __syncthreads();

#pragma unroll
    for (int kc = 0; kc < 2; kc++) {
        u32 sa = sb + PW_A + kc * 36864;
        u32 sbb = sb + PW_B + kc * 73728;
#pragma unroll
        for (int ks = 0; ks < 4; ks++) {
            u32 ah[2][4], al[2][4];
#pragma unroll
            for (int mt = 0; mt < 2; mt++) {
                ldsm4(ah[mt], sa + aoff + mt * 2304 + ks * 32);
                ldsm4(al[mt], sa + 18432 + aoff + mt * 2304 + ks * 32);
            }
#pragma unroll
            for (int ng = 0; ng < 4; ng++) {
                u32 bh[4], bl[4];
                ldsm4(bh, sbb + boff + ng * 2304 + ks * 32);
                ldsm4(bl, sbb + 36864 + boff + ng * 2304 + ks * 32);
#pragma unroll
                for (int mt = 0; mt < 2; mt++) {
                    mma_bf16(acc[mt][ng * 2 + 0], ah[mt], bh[0], bh[1]);
                    mma_bf16(acc[mt][ng * 2 + 1], ah[mt], bh[2], bh[3]);
                    mma_bf16(acc[mt][ng * 2 + 0], ah[mt], bl[0], bl[1]);
                    mma_bf16(acc[mt][ng * 2 + 1], ah[mt], bl[2], bl[3]);
                    mma_bf16(acc[mt][ng * 2 + 0], al[mt], bh[0], bh[1]);
                    mma_bf16(acc[mt][ng * 2 + 1], al[mt], bh[2], bh[3]);
                }
            }
        }
    }

    float* ob = g_xp + (size_t)b * C2 * HWP;
#pragma unroll
    for (int mt = 0; mt < 2; mt++) {
#pragma unroll
        for (int j = 0; j < 8; j++) {
#pragma unroll
            for (int r = 0; r < 4; r++) {
                int o = n_base + j * 8 + (lane & 3) * 2 + (r & 1);
                int opix = rp * 128 + m_base + mt * 16 + (lane >> 2) + (r >> 1) * 8;
                ob[(size_t)o * HWP + opix] = acc[mt][j][r] * g_scale[o] + g_bias[o];
            }
        }
    }
}

// ======================= stage 2: 3x3 offset conv (HMMA fp16 2-pass) =======================
__global__ void __launch_bounds__(512, 1) offconv_mma_kernel(const float* __restrict__ off_b) {
    extern __shared__ __align__(16) char smem[];
    u32 sb = smem_u32(smem);

    int t = threadIdx.x;
    int lane = t & 31;
    int warp = t >> 5;
    int rp = blockIdx.x;
    int b = blockIdx.y;

    int m_base = (warp & 3) * 32;
    int n_base = (warp >> 2) * 8;
    u32 aoff = (u32)((m_base + (lane & 7) + ((lane >> 3) & 1) * 8) * 144 + (lane >> 4) * 16);
    u32 boff = (u32)((n_base + (lane & 7)) * 144 + (lane >> 3) * 16);

    float acc[2][4];
#pragma unroll
    for (int i = 0; i < 2; i++)
#pragma unroll
        for (int r = 0; r < 4; r++) acc[i][r] = 0.f;

    int m = t & 127;
    int kq = t >> 7;
    int hrow = rp * 2 + (m >> 6);
    int wcol = m & 63;
    const float* xpb = g_xp + (size_t)b * C2 * HWP;

    auto gather = [&](int cc, int abuf) {
        int n_ = cc >> 2, kc = cc & 3;
        int hs = hrow + (n_ / 3 - 1);
        int ws = wcol + (n_ % 3 - 1);
        bool inb = ((unsigned)hs < 64u) && ((unsigned)ws < 64u);
        const float* src = xpb + (size_t)(kc * 64 + kq * 16) * HWP + hs * WW + ws;
        u32 hi[8], lo[8];
#pragma unroll
        for (int j2 = 0; j2 < 8; j2++) {
            float v0 = inb ? src[(size_t)(2 * j2) * HWP] : 0.f;
            float v1 = inb ? src[(size_t)(2 * j2 + 1) * HWP] : 0.f;
            split2h(v0, v1, hi[j2], lo[j2]);
        }
        char* ab = smem + OC_A + abuf * 36864 + m * 144 + kq * 32;
        *(uint4*)ab = make_uint4(hi[0], hi[1], hi[2], hi[3]);
        *(uint4*)(ab + 16) = make_uint4(hi[4], hi[5], hi[6], hi[7]);
        *(uint4*)(ab + 18432) = make_uint4(lo[0], lo[1], lo[2], lo[3]);
        *(uint4*)(ab + 18432 + 16) = make_uint4(lo[4], lo[5], lo[6], lo[7]);
    };

    {
        const char* src = (const char*)g_ow;
        for (int u = t; u < 288; u += 512)
            if (u < 288) cpa16(sb + OC_B + u * 16, src + u * 16);
        cpa_commit();
    }
    gather(0, 0);

    for (int cc = 0; cc < 36; cc++) {
        int abuf = cc & 1;
        __syncthreads();

        if (cc + 1 < 36) {
            const char* src = (const char*)g_ow + (size_t)(cc + 1) * 4608;
            u32 dst = sb + OC_B + ((cc + 1) & 1) * 4608;
            for (int u = t; u < 288; u += 512)
                if (u < 288) cpa16(dst + u * 16, src + u * 16);
        }
        cpa_commit();
        if (cc + 1 < 36) gather(cc + 1, abuf ^ 1);
        cpa_wait1();

        u32 sa = sb + OC_A + abuf * 36864;
        u32 sbb = sb + OC_B + abuf * 4608;
#pragma unroll
        for (int kk = 0; kk < 2; kk++) {
            u32 bh[4];
            ldsm4(bh, sbb + boff + kk * 64);
#pragma unroll
            for (int ksh = 0; ksh < 2; ksh++) {
                int ks = kk * 2 + ksh;
                u32 ah[2][4], al[2][4];
#pragma unroll
                for (int mt = 0; mt < 2; mt++) {
                    ldsm4(ah[mt], sa + aoff + mt * 2304 + ks * 32);
                    ldsm4(al[mt], sa + 18432 + aoff + mt * 2304 + ks * 32);
                }
#pragma unroll
                for (int mt = 0; mt < 2; mt++) {
                    mma_f16(acc[mt], ah[mt], bh[2 * ksh], bh[2 * ksh + 1]);
                    mma_f16(acc[mt], al[mt], bh[2 * ksh], bh[2 * ksh + 1]);
                }
            }
        }
    }

    float* ob = g_off + (size_t)b * 18 * HWP;
#pragma unroll
    for (int mt = 0; mt < 2; mt++) {
#pragma unroll
        for (int r = 0; r < 4; r++) {
            int o = n_base + (lane & 3) * 2 + (r & 1);
            int opix = rp * 128 + m_base + mt * 16 + (lane >> 2) + (r >> 1) * 8;
            if (o < 18)
                ob[(size_t)o * HWP + opix] = acc[mt][r] + off_b[o];
        }
    }
}

// ======================= stage 3: warp-specialized dcn, pipelined producer =======================
// 640 threads: warps 0..15 consumers (pure ldsm+mma), warps 16..19 producers (1 thread/pixel).
// Producer is explicitly software-pipelined: 8 batches of 8 channels, ping-pong register
// double buffer — batch k+1's 32 LDGs issue BEFORE batch k's bilinear/split/STS, keeping
// MLP ~32-64 per warp so the 234-cyc L2 latency is paid once per chunk, not per batch.
__global__ void __launch_bounds__(640, 1) dcn_mma_kernel(float* __restrict__ out) {
    extern __shared__ __align__(16) char smem[];
    u32 sb = smem_u32(smem);

    int t = threadIdx.x;
    int rp = blockIdx.x;
    int b = blockIdx.y;

    const float* xpb = g_xp + (size_t)b * C2 * HWP;

    if (t >= 512) {
        // ---------------- producer warps ----------------
        int g = t - 512;                // pixel 0..127
        int pix = rp * 128 + g;
        int hrow = rp * 2 + (g >> 6);
        int pcol = g & 63;
        const float* offb = g_off + (size_t)b * 18 * HWP;

        auto produce = [&](int cc) {
            int n_ = cc >> 2, kc = cc & 3;
            float oy = offb[n_ * HWP + pix];
            float ox = offb[(n_ + 9) * HWP + pix];
            float py = (float)hrow + (float)(n_ / 3 - 1) + oy;
            float px = (float)pcol + (float)(n_ % 3 - 1) + ox;
            py = fminf(fmaxf(py, 0.f), 63.f);
            px = fminf(fmaxf(px, 0.f), 63.f);
            float y0f = floorf(py), x0f = floorf(px);
            int y0 = (int)y0f, x0 = (int)x0f;
            int x1 = min(x0 + 1, 63);
            int y0o = y0 * WW, y1o = min(y0 + 1, 63) * WW;
            float wy = py - y0f, wx = px - x0f;
            float w00 = (1.f - wy) * (1.f - wx);
            float w01 = (1.f - wy) * wx;
            float w10 = wy * (1.f - wx);
            float w11 = wy * wx;

            const float* plane = xpb + (size_t)(kc * 64) * HWP;
            char* ab = smem + SM_A + (cc & 1) * 36864 + g * 144;

            float r0[8][4], r1[8][4];
            // prologue: issue batch 0 (channels 0..7)
#pragma unroll
            for (int e = 0; e < 8; e++) {
                const float* q = plane + (size_t)e * HWP;
                r0[e][0] = q[y0o + x0]; r0[e][1] = q[y0o + x1];
                r0[e][2] = q[y1o + x0]; r0[e][3] = q[y1o + x1];
            }
#pragma unroll
            for (int k = 0; k < 8; k++) {
                float (*cur)[4] = (k & 1) ? r1 : r0;
                float (*nxt)[4] = (k & 1) ? r0 : r1;
                if (k + 1 < 8) {
                    const float* pn = plane + (size_t)((k + 1) * 8) * HWP;
#pragma unroll
                    for (int e = 0; e < 8; e++) {
                        const float* q = pn + (size_t)e * HWP;
                        nxt[e][0] = q[y0o + x0]; nxt[e][1] = q[y0o + x1];
                        nxt[e][2] = q[y1o + x0]; nxt[e][3] = q[y1o + x1];
                    }
                }
                u32 h[4], l[4];
#pragma unroll
                for (int e2 = 0; e2 < 4; e2++) {
                    float v0 = cur[2 * e2][0] * w00 + cur[2 * e2][1] * w01
                             + cur[2 * e2][2] * w10 + cur[2 * e2][3] * w11;
                    float v1 = cur[2 * e2 + 1][0] * w00 + cur[2 * e2 + 1][1] * w01
                             + cur[2 * e2 + 1][2] * w10 + cur[2 * e2 + 1][3] * w11;
                    split2h(v0, v1, h[e2], l[e2]);
                }
                *(uint4*)(ab + k * 16) = make_uint4(h[0], h[1], h[2], h[3]);
                *(uint4*)(ab + 18432 + k * 16) = make_uint4(l[0], l[1], l[2], l[3]);
            }
        };

        // prologue: B(0) + A(0)
        {
            const char* src = (const char*)g_bt;
            for (int u = g; u < 2304; u += 128)
                cpa16(sb + SM_B + u * 16, src + u * 16);
            cpa_commit();
        }
        produce(0);
        cpa_wait0();
        __syncthreads();   // publish A(0)/B(0)

        for (int cc = 0; cc < 36; cc++) {
            if (cc + 1 < 36) {
                const char* srcB = (const char*)g_bt + (size_t)(cc + 1) * 36864;
                u32 dst = sb + SM_B + ((cc + 1) & 1) * 36864;
                for (int u = g; u < 2304; u += 128)
                    cpa16(dst + u * 16, srcB + u * 16);
                cpa_commit();
                produce(cc + 1);
                cpa_wait0();
            }
            __syncthreads();   // publish A(cc+1)/B(cc+1); consumers done with buf cc
        }
        return;
    }

    // ---------------- consumer warps ----------------
    int lane = t & 31;
    int warp = t >> 5;
    int m_base = (warp & 3) * 32;
    int n_base = (warp >> 2) * 64;
    u32 aoff = (u32)((m_base + (lane & 7) + ((lane >> 3) & 1) * 8) * 144 + (lane >> 4) * 16);
    u32 boff = (u32)((n_base + (lane & 7) + (lane >> 4) * 8) * 144 + ((lane >> 3) & 1) * 16);

    float acc[2][8][4];
#pragma unroll
    for (int i = 0; i < 2; i++)
#pragma unroll
        for (int j = 0; j < 8; j++)
#pragma unroll
            for (int r = 0; r < 4; r++) acc[i][j][r] = 0.f;

    __syncthreads();   // wait A(0)/B(0)

    for (int cc = 0; cc < 36; cc++) {
        u32 sa = sb + SM_A + (cc & 1) * 36864;
        u32 sbb = sb + SM_B + (cc & 1) * 36864;
#pragma unroll
        for (int p = 0; p < 4; p++) {
            u32 ah[2][4], al[2][4];
#pragma unroll
            for (int mt = 0; mt < 2; mt++) {
                ldsm4(ah[mt], sa + aoff + mt * 2304 + p * 32);
                ldsm4(al[mt], sa + 18432 + aoff + mt * 2304 + p * 32);
            }
#pragma unroll
            for (int ng = 0; ng < 4; ng++) {
                u32 bh[4];
                ldsm4(bh, sbb + boff + ng * 2304 + p * 32);
#pragma unroll
                for (int mt = 0; mt < 2; mt++) {
                    mma_f16(acc[mt][ng * 2 + 0], ah[mt], bh[0], bh[1]);
                    mma_f16(acc[mt][ng * 2 + 1], ah[mt], bh[2], bh[3]);
                    mma_f16(acc[mt][ng * 2 + 0], al[mt], bh[0], bh[1]);
                    mma_f16(acc[mt][ng * 2 + 1], al[mt], bh[2], bh[3]);
                }
            }
        }
        __syncthreads();   // done with buf cc; producers publish cc+1
    }

    // epilogue: SiLU + store
    float* ob = out + (size_t)b * C2 * HWP;
#pragma unroll
    for (int mt = 0; mt < 2; mt++) {
#pragma unroll
        for (int j = 0; j < 8; j++) {
#pragma unroll
            for (int r = 0; r < 4; r++) {
                int o = n_base + j * 8 + (lane & 3) * 2 + (r & 1);
                int opix = rp * 128 + m_base + mt * 16 + (lane >> 2) + (r >> 1) * 8;
                float f = acc[mt][j][r];
                f = f / (1.f + __expf(-f));
                ob[(size_t)o * HWP + opix] = f;
            }
        }
    }
}

// ======================= launch =======================
extern "C" void kernel_launch(void* const* d_in, const int* in_sizes, int n_in,
                              void* d_out, int out_size) {
    const float* x = (const float*)d_in[0];
    const float* pw_w = (const float*)d_in[1];
    const float* gamma = (const float*)d_in[2];
    const float* beta = (const float*)d_in[3];
    const float* mean = (const float*)d_in[4];
    const float* var = (const float*)d_in[5];
    const float* off_w = (const float*)d_in[6];
    const float* off_b = (const float*)d_in[7];
    const float* dcn_w = (const float*)d_in[8];
    float* out = (float*)d_out;

    (void)in_sizes; (void)n_in; (void)out_size;

    cudaFuncSetAttribute(pw_mma_kernel, cudaFuncAttributeMaxDynamicSharedMemorySize, PW_DYN);
    cudaFuncSetAttribute(offconv_mma_kernel, cudaFuncAttributeMaxDynamicSharedMemorySize, OC_DYN);
    cudaFuncSetAttribute(dcn_mma_kernel, cudaFuncAttributeMaxDynamicSharedMemorySize, SM_DYN);

    prep_all<<<38, 256>>>(gamma, beta, mean, var, pw_w, dcn_w, off_w);
    pw_mma_kernel<<<dim3(32, BB), 512, PW_DYN>>>(x);
    offconv_mma_kernel<<<dim3(32, BB), 512, OC_DYN>>>(off_b);
    dcn_mma_kernel<<<dim3(32, BB), 640, SM_DYN>>>(out);
}